// round 9
// baseline (speedup 1.0000x reference)
#include <cuda_runtime.h>
#include <cuda_fp16.h>
#include <stdint.h>

#define T_STEPS 8192
#define INPUT_D 1024
#define TRACE_D 64
#define CTX_D   16
#define OUT_D   1024
#define CH      (TRACE_D*CTX_D)      /* 1024 channels */
#define CHUNK   64
#define NCHUNK  (T_STEPS/CHUNK)      /* 128 */

/* ------------------------------------------------------------------ */
/* scratch (device globals: allocation-free rule)                      */
/* ------------------------------------------------------------------ */
__device__ float  g_gx[T_STEPS*TRACE_D];      /* gated_x                */
__device__ float2 g_Ac[NCHUNK*CH];
__device__ float2 g_Bc[NCHUNK*CH];
__device__ float2 g_carry[NCHUNK*CH];
__device__ float  g_zr [(size_t)T_STEPS*OUT_D];
__device__ float  g_gs [(size_t)T_STEPS*2*OUT_D];   /* go|skip fused, N=2048 */
__device__ unsigned char g_start[T_STEPS];
__device__ float  g_fsdump[2*CH];
__device__ float  g_bgs[2*OUT_D];             /* go_b | skip_b          */

/* fp16 operands for tensor-core GEMMs */
__device__ __half g_xh[(size_t)T_STEPS*INPUT_D];    /* x hi (also dual-A) */
__device__ __half g_xl[(size_t)T_STEPS*INPUT_D];    /* x lo (small gemm)  */
__device__ __half g_zf[(size_t)T_STEPS*2*CH];       /* z_in fp16          */
__device__ __half g_gsf[2*OUT_D*INPUT_D];           /* go|skip weights    */
__device__ __half g_mxf[OUT_D*2*CH];                /* mix weights        */
__device__ __half g_wch[128*INPUT_D], g_wcl[128*INPUT_D]; /* gi|pre hi/lo */

/* ------------------------------------------------------------------ */
/* PTX helpers (baseline ISA only: cp.async / ldmatrix / mma.sync)     */
/* ------------------------------------------------------------------ */
__device__ __forceinline__ uint32_t smem_u32(const void* p){
    uint32_t a;
    asm("{ .reg .u64 t; cvta.to.shared.u64 t, %1; cvt.u32.u64 %0, t; }"
        : "=r"(a) : "l"(p));
    return a;
}
__device__ __forceinline__ void cpa16(uint32_t s, const void* g){
    asm volatile("cp.async.cg.shared.global [%0], [%1], 16;"
                 :: "r"(s), "l"(g) : "memory");
}
__device__ __forceinline__ void cpa_commit(){
    asm volatile("cp.async.commit_group;" ::: "memory");
}
template<int N>
__device__ __forceinline__ void cpa_wait(){
    asm volatile("cp.async.wait_group %0;" :: "n"(N) : "memory");
}
__device__ __forceinline__ void ldsm4(uint32_t* r, uint32_t a){
    asm volatile("ldmatrix.sync.aligned.m8n8.x4.shared.b16 {%0,%1,%2,%3}, [%4];"
                 : "=r"(r[0]), "=r"(r[1]), "=r"(r[2]), "=r"(r[3]) : "r"(a));
}
__device__ __forceinline__ void mma_f16(float* d, const uint32_t* a, const uint32_t* b){
    asm volatile(
        "mma.sync.aligned.m16n8k16.row.col.f32.f16.f16.f32 "
        "{%0,%1,%2,%3}, {%4,%5,%6,%7}, {%8,%9}, {%0,%1,%2,%3};"
        : "+f"(d[0]), "+f"(d[1]), "+f"(d[2]), "+f"(d[3])
        : "r"(a[0]), "r"(a[1]), "r"(a[2]), "r"(a[3]), "r"(b[0]), "r"(b[1]));
}
__device__ __forceinline__ uint32_t sw128(uint32_t b){
    return b ^ ((b >> 3) & 0x70);
}

#define BIG_SMEM   (3*32768)                   /* 98304: 2 CTAs/SM      */
#define SMALL_SMEM (3*(2*8192 + 2*16384))      /* 147456                */

/* ------------------------------------------------------------------ */
/* big GEMM, fp16 single-pass, fp32 acc.  C[M,N] = A@W^T + bias        */
/* tile 128x128, K-chunk 64, 3-stage cp.async, 2 CTAs/SM.              */
/* grid = (M/128, N/128)                                               */
/* ------------------------------------------------------------------ */
__global__ __launch_bounds__(256, 2)
void hgemm_big(const __half* __restrict__ A, const __half* __restrict__ W,
               const float* __restrict__ bias, float* __restrict__ C,
               int N, int K)
{
    const int TSZ = 16384, STAGE = 32768;
    extern __shared__ char smem[];
    const uint32_t sb = smem_u32(smem);
    const int tid = threadIdx.x;
    const int wid = tid >> 5, l = tid & 31;
    const int bm = blockIdx.x * 128, bn = blockIdx.y * 128;
    const int wm0 = (wid & 3) * 32, wn0 = (wid >> 2) * 64;

    float acc[2][8][4];
#pragma unroll
    for (int mt = 0; mt < 2; mt++)
#pragma unroll
        for (int nt = 0; nt < 8; nt++)
#pragma unroll
            for (int j = 0; j < 4; j++) acc[mt][nt][j] = 0.f;

    const int nk = K >> 6;

    auto issue = [&](int s, int k0){
        const uint32_t st = sb + s * STAGE;
#pragma unroll
        for (int it = 0; it < 4; it++) {
            int idx = tid + it*256;
            int row = idx >> 3, cv = idx & 7;
            uint32_t sw = sw128((uint32_t)(row*128 + cv*16));
            cpa16(st +       sw, A + (size_t)(bm + row) * K + k0 + cv*8);
            cpa16(st + TSZ + sw, W + (size_t)(bn + row) * K + k0 + cv*8);
        }
        cpa_commit();
    };

    issue(0, 0);
    issue(1, 64);
    for (int kt = 0; kt < nk; kt++) {
        if (kt + 1 < nk) cpa_wait<1>(); else cpa_wait<0>();
        __syncthreads();
        if (kt + 2 < nk) issue((kt+2) % 3, (kt+2) << 6);

        const uint32_t st  = sb + (kt % 3) * STAGE;
        const uint32_t A_s = st, B_s = st + TSZ;

#pragma unroll
        for (int kk = 0; kk < 4; kk++) {
            uint32_t af[2][4];
#pragma unroll
            for (int mt = 0; mt < 2; mt++) {
                int row = wm0 + mt*16 + (l & 15);
                uint32_t sw = sw128((uint32_t)(row*128 + kk*32 + (l >> 4)*16));
                ldsm4(af[mt], A_s + sw);
            }
            uint32_t bf[4][4];
#pragma unroll
            for (int p = 0; p < 4; p++) {
                int row = wn0 + p*16 + ((l >> 4) & 1)*8 + (l & 7);
                uint32_t sw = sw128((uint32_t)(row*128 + kk*32 + ((l >> 3) & 1)*16));
                ldsm4(bf[p], B_s + sw);
            }
#pragma unroll
            for (int mt = 0; mt < 2; mt++)
#pragma unroll
                for (int nt = 0; nt < 8; nt++)
                    mma_f16(acc[mt][nt], af[mt], &bf[nt >> 1][(nt & 1)*2]);
        }
    }

#pragma unroll
    for (int mt = 0; mt < 2; mt++) {
        int row0 = bm + wm0 + mt*16 + (l >> 2);
#pragma unroll
        for (int nt = 0; nt < 8; nt++) {
            int col = bn + wn0 + nt*8 + (l & 3)*2;
            float bb0 = bias[col], bb1 = bias[col+1];
            float* c0 = C + (size_t)row0 * N + col;
            c0[0] = acc[mt][nt][0] + bb0;
            c0[1] = acc[mt][nt][1] + bb1;
            float* c1 = C + (size_t)(row0 + 8) * N + col;
            c1[0] = acc[mt][nt][2] + bb0;
            c1[1] = acc[mt][nt][3] + bb1;
        }
    }
}

/* ------------------------------------------------------------------ */
/* small GEMM (BM=64, N=128, K=1024), fp16 hi/lo 3-pass (protects      */
/* final_state precision), FUSED gated epilogue -> g_gx                */
/* ------------------------------------------------------------------ */
__global__ __launch_bounds__(256, 1)
void hgemm_small_gated(const __half* __restrict__ Ah, const __half* __restrict__ Al,
                       const __half* __restrict__ Wh, const __half* __restrict__ Wl,
                       const float* __restrict__ gi_b, const float* __restrict__ pre_b)
{
    const int ASZ = 8192, STAGE = 2*ASZ + 2*16384, K = INPUT_D;
    extern __shared__ char smem[];
    const uint32_t sb = smem_u32(smem);
    const int tid = threadIdx.x;
    const int wid = tid >> 5, l = tid & 31;
    const int bm = blockIdx.x * 64;
    const int wm0 = (wid & 3) * 16, wn0 = (wid >> 2) * 64;
    const int lr = tid >> 3, lc = tid & 7;

    float acc[8][4];
#pragma unroll
    for (int nt = 0; nt < 8; nt++)
#pragma unroll
        for (int j = 0; j < 4; j++) acc[nt][j] = 0.f;

    const int nk = K >> 6;       /* 16 */

    auto issue = [&](int s, int k0){
        const uint32_t st = sb + s * STAGE;
#pragma unroll
        for (int it = 0; it < 2; it++) {
            int idx = tid + it*256;
            int row = idx >> 3, cv = idx & 7;
            uint32_t sw = sw128((uint32_t)(row*128 + cv*16));
            size_t ao = (size_t)(bm + row) * K + k0 + cv*8;
            cpa16(st +       sw, Ah + ao);
            cpa16(st + ASZ + sw, Al + ao);
        }
#pragma unroll
        for (int it = 0; it < 4; it++) {
            int row = lr + it*32, cv = lc;
            uint32_t sw = sw128((uint32_t)(row*128 + cv*16));
            size_t bo = (size_t)row * K + k0 + cv*8;
            cpa16(st + 2*ASZ +         sw, Wh + bo);
            cpa16(st + 2*ASZ + 16384 + sw, Wl + bo);
        }
        cpa_commit();
    };

    issue(0, 0);
    issue(1, 64);
    for (int kt = 0; kt < nk; kt++) {
        if (kt + 1 < nk) cpa_wait<1>(); else cpa_wait<0>();
        __syncthreads();
        if (kt + 2 < nk) issue((kt+2) % 3, (kt+2) << 6);

        const uint32_t st  = sb + (kt % 3) * STAGE;
        const uint32_t A_h = st, A_l = st + ASZ, B_h = st + 2*ASZ, B_l = st + 2*ASZ + 16384;

#pragma unroll
        for (int kk = 0; kk < 4; kk++) {
            uint32_t ah[4], al[4];
            {
                int row = wm0 + (l & 15);
                uint32_t sw = sw128((uint32_t)(row*128 + kk*32 + (l >> 4)*16));
                ldsm4(ah, A_h + sw);
                ldsm4(al, A_l + sw);
            }
            uint32_t bh[4][4], bl[4][4];
#pragma unroll
            for (int p = 0; p < 4; p++) {
                int row = wn0 + p*16 + ((l >> 4) & 1)*8 + (l & 7);
                uint32_t sw = sw128((uint32_t)(row*128 + kk*32 + ((l >> 3) & 1)*16));
                ldsm4(bh[p], B_h + sw);
                ldsm4(bl[p], B_l + sw);
            }
#pragma unroll
            for (int nt = 0; nt < 8; nt++) {
                const uint32_t* bhp = &bh[nt >> 1][(nt & 1)*2];
                const uint32_t* blp = &bl[nt >> 1][(nt & 1)*2];
                mma_f16(acc[nt], ah, bhp);
                mma_f16(acc[nt], ah, blp);
                mma_f16(acc[nt], al, bhp);
            }
        }
    }

    /* fused epilogue: stage Y into smem, then compute gated_x */
    __syncthreads();
    float* sY = (float*)smem;              /* [64][130] */
    const int YS = 130;
    {
        int row0 = wm0 + (l >> 2);
#pragma unroll
        for (int nt = 0; nt < 8; nt++) {
            int col = wn0 + nt*8 + (l & 3)*2;
            sY[row0*YS + col]     = acc[nt][0];
            sY[row0*YS + col + 1] = acc[nt][1];
            sY[(row0+8)*YS + col]     = acc[nt][2];
            sY[(row0+8)*YS + col + 1] = acc[nt][3];
        }
    }
    __syncthreads();
    const int m = tid & 63;
    const float gb = gi_b[m], pb = pre_b[m];
#pragma unroll
    for (int i = 0; i < 16; i++) {
        int r = (tid >> 6) + i*4;
        float y1 = sY[r*YS + m]      + gb;
        float y2 = sY[r*YS + 64 + m] + pb;
        g_gx[(size_t)(bm + r)*TRACE_D + m] = y2 / (1.f + expf(-y1));
    }
}

/* ------------------------------------------------------------------ */
/* merged conversion kernel                                            */
/* ------------------------------------------------------------------ */
#define XQ  2097152
#define WQ  16384
#define GQ  262144
#define MQ  524288
#define C1q (XQ)
#define C2q (C1q + WQ)
#define C3q (C2q + WQ)
#define C4q (C3q + GQ)
#define C5q (C4q + GQ)
#define C6q (C5q + MQ)
#define CTq (C6q + 512)

__device__ __forceinline__ void split_hl(const float4* __restrict__ s, long i,
                                         uint2* __restrict__ h, uint2* __restrict__ l)
{
    float4 v = s[i];
    __half h0 = __float2half(v.x), h1 = __float2half(v.y);
    __half h2 = __float2half(v.z), h3 = __float2half(v.w);
    __half l0 = __float2half(v.x - __half2float(h0));
    __half l1 = __float2half(v.y - __half2float(h1));
    __half l2 = __float2half(v.z - __half2float(h2));
    __half l3 = __float2half(v.w - __half2float(h3));
    uint2 uh, ul;
    uh.x = (uint32_t)__half_as_ushort(h0) | ((uint32_t)__half_as_ushort(h1) << 16);
    uh.y = (uint32_t)__half_as_ushort(h2) | ((uint32_t)__half_as_ushort(h3) << 16);
    ul.x = (uint32_t)__half_as_ushort(l0) | ((uint32_t)__half_as_ushort(l1) << 16);
    ul.y = (uint32_t)__half_as_ushort(l2) | ((uint32_t)__half_as_ushort(l3) << 16);
    h[i] = uh; l[i] = ul;
}
__device__ __forceinline__ void cvt_h(const float4* __restrict__ s, long i,
                                      uint2* __restrict__ o)
{
    float4 v = s[i];
    uint2 u;
    u.x = (uint32_t)__half_as_ushort(__float2half(v.x))
        | ((uint32_t)__half_as_ushort(__float2half(v.y)) << 16);
    u.y = (uint32_t)__half_as_ushort(__float2half(v.z))
        | ((uint32_t)__half_as_ushort(__float2half(v.w)) << 16);
    o[i] = u;
}

__global__ void split_all(const float* __restrict__ x,
                          const float* __restrict__ gi_w, const float* __restrict__ pre_w,
                          const float* __restrict__ go_w, const float* __restrict__ skip_w,
                          const float* __restrict__ mix_w,
                          const float* __restrict__ go_b, const float* __restrict__ skip_b)
{
    long i = (long)blockIdx.x * blockDim.x + threadIdx.x;
    if (i >= CTq) return;
    if (i < C1q)      split_hl((const float4*)x,     i,       (uint2*)g_xh,  (uint2*)g_xl);
    else if (i < C2q) split_hl((const float4*)gi_w,  i - C1q, (uint2*)g_wch, (uint2*)g_wcl);
    else if (i < C3q) split_hl((const float4*)pre_w, i - C2q,
                               (uint2*)(g_wch + 64*INPUT_D), (uint2*)(g_wcl + 64*INPUT_D));
    else if (i < C4q) cvt_h((const float4*)go_w,   i - C3q, (uint2*)g_gsf);
    else if (i < C5q) cvt_h((const float4*)skip_w, i - C4q,
                            (uint2*)(g_gsf + (size_t)OUT_D*INPUT_D));
    else if (i < C6q) cvt_h((const float4*)mix_w,  i - C5q, (uint2*)g_mxf);
    else {
        long i2 = i - C6q;
        float4 v = (i2 < 256) ? ((const float4*)go_b)[i2] : ((const float4*)skip_b)[i2 - 256];
        ((float4*)g_bgs)[i2] = v;
    }
}

/* ------------------------------------------------------------------ */
/* start-flag canonicalization, single block                           */
/* ------------------------------------------------------------------ */
__global__ __launch_bounds__(1024)
void prep_start(const unsigned char* __restrict__ s8)
{
    __shared__ int flags[3];
    const int tid = threadIdx.x;
    if (tid < 3) flags[tid] = 0;
    __syncthreads();
    const unsigned int* s32 = (const unsigned int*)s8;
    for (int i = tid; i < 2048; i += 1024) {
        unsigned v = s32[i];
        if (v == 0u) continue;
        else if (v == 1u)           atomicOr(&flags[0], 1);
        else if (v == 0x3f800000u)  atomicOr(&flags[1], 1);
        else                        atomicOr(&flags[2], 1);
    }
    __syncthreads();
    const int mode = flags[2] ? 0 : (flags[1] ? 2 : (flags[0] ? 1 : 0));
#pragma unroll
    for (int i = 0; i < 8; i++) {
        int idx = tid + i*1024;
        unsigned char v;
        if (mode == 1)      v = (((const int*)  s8)[idx] != 0);
        else if (mode == 2) v = (((const float*)s8)[idx] != 0.f);
        else                v = (s8[idx] != 0);
        g_start[idx] = v;
    }
}

/* ------------------------------------------------------------------ */
/* Phase A: per-chunk affine composition (CHUNK=64, 128 blocks)        */
/* ------------------------------------------------------------------ */
__global__ __launch_bounds__(1024)
void scan_chunks(const float* __restrict__ ffa_a, const float* __restrict__ ffa_b)
{
    __shared__ float sx[CHUNK*TRACE_D];
    __shared__ unsigned char ss[CHUNK];
    const int chunk = blockIdx.x, tid = threadIdx.x;
    const float* src = g_gx + chunk*CHUNK*TRACE_D;
    for (int i = tid; i < CHUNK*TRACE_D; i += 1024) sx[i] = src[i];
    if (tid < CHUNK) ss[tid] = g_start[chunk*CHUNK + tid];
    __syncthreads();

    const int m = tid >> 4, c = tid & 15;
    const float r  = expf(-fabsf(ffa_a[m]));
    const float gr = r * cosf(ffa_b[c]);
    const float gi = r * sinf(ffa_b[c]);

    float Ar = 1.f, Ai = 0.f, Br = 0.f, Bi = 0.f;
#pragma unroll 4
    for (int t = 0; t < CHUNK; t++) {
        float xv = sx[t*TRACE_D + m];
        if (ss[t]) { Ar = 0.f; Ai = 0.f; Br = xv; Bi = 0.f; }
        else {
            float nAr = gr*Ar - gi*Ai, nAi = gr*Ai + gi*Ar;
            float nBr = gr*Br - gi*Bi + xv, nBi = gr*Bi + gi*Br;
            Ar = nAr; Ai = nAi; Br = nBr; Bi = nBi;
        }
    }
    g_Ac[chunk*CH + tid] = make_float2(Ar, Ai);
    g_Bc[chunk*CH + tid] = make_float2(Br, Bi);
}

/* Phase B: sequential carry over 128 chunks; emits final_state.       */
__global__ __launch_bounds__(1024)
void carry_kernel(const float* __restrict__ st_re, const float* __restrict__ st_im,
                  float* __restrict__ out_fs, int fs_mode)
{
    const int tid = threadIdx.x;
    float sr = st_re[tid], si = st_im[tid];
    for (int j0 = 0; j0 < NCHUNK; j0 += 8) {
        float2 a[8], b[8];
#pragma unroll
        for (int u = 0; u < 8; u++) { a[u] = g_Ac[(j0+u)*CH + tid]; b[u] = g_Bc[(j0+u)*CH + tid]; }
#pragma unroll
        for (int u = 0; u < 8; u++) {
            g_carry[(j0+u)*CH + tid] = make_float2(sr, si);
            float nr = a[u].x*sr - a[u].y*si + b[u].x;
            float ni = a[u].x*si + a[u].y*sr + b[u].y;
            sr = nr; si = ni;
        }
    }
    if (fs_mode == 1) {
        out_fs[tid] = sr;
    } else {
        out_fs[2*tid]   = sr;
        out_fs[2*tid+1] = si;
    }
}

/* Phase C: replay chunks; write z_in fp16 [T, 2048]                   */
__global__ __launch_bounds__(1024)
void expand_kernel(const float* __restrict__ ffa_a, const float* __restrict__ ffa_b)
{
    __shared__ float sx[CHUNK*TRACE_D];
    __shared__ unsigned char ss[CHUNK];
    const int chunk = blockIdx.x, tid = threadIdx.x;
    const float* src = g_gx + chunk*CHUNK*TRACE_D;
    for (int i = tid; i < CHUNK*TRACE_D; i += 1024) sx[i] = src[i];
    if (tid < CHUNK) ss[tid] = g_start[chunk*CHUNK + tid];
    __syncthreads();

    const int m = tid >> 4, c = tid & 15;
    const float r  = expf(-fabsf(ffa_a[m]));
    const float gr = r * cosf(ffa_b[c]);
    const float gi = r * sinf(ffa_b[c]);

    float2 s = g_carry[chunk*CH + tid];
    const size_t zo = (size_t)chunk*CHUNK*2*CH + m*32 + c;
#pragma unroll 2
    for (int t = 0; t < CHUNK; t++) {
        float xv = sx[t*TRACE_D + m];
        float nr, ni;
        if (ss[t]) { nr = xv; ni = 0.f; }
        else { nr = gr*s.x - gi*s.y + xv; ni = gr*s.y + gi*s.x; }
        s.x = nr; s.y = ni;
        size_t o = zo + (size_t)t*2048;
        g_zf[o]      = __float2half(nr);
        g_zf[o + 16] = __float2half(ni);
    }
}

/* ------------------------------------------------------------------ */
/* epilogue: zg = z*sig(go); LN(zg) + skip*(1-sig(go))                 */
/* ------------------------------------------------------------------ */
__global__ __launch_bounds__(256)
void ln_kernel(float* __restrict__ out)
{
    const int row = blockIdx.x, tid = threadIdx.x;
    const float* zp = g_zr + (size_t)row*OUT_D;
    const float* gp = g_gs + (size_t)row*2*OUT_D;
    const float* sp = gp + OUT_D;

    float zg[4], sk[4], s1 = 0.f, s2 = 0.f;
#pragma unroll
    for (int i = 0; i < 4; i++) {
        int c = tid + i*256;
        float g  = 1.f / (1.f + expf(-gp[c]));
        float zv = zp[c] * g;
        zg[i] = zv; s1 += zv; s2 += zv*zv;
        sk[i] = sp[c] * (1.f - g);
    }
#pragma unroll
    for (int o = 16; o > 0; o >>= 1) {
        s1 += __shfl_xor_sync(0xffffffffu, s1, o);
        s2 += __shfl_xor_sync(0xffffffffu, s2, o);
    }
    __shared__ float sh1[8], sh2[8];
    const int warp = tid >> 5, lane = tid & 31;
    if (lane == 0) { sh1[warp] = s1; sh2[warp] = s2; }
    __syncthreads();
    if (tid == 0) {
        float t1 = 0.f, t2 = 0.f;
        for (int w = 0; w < 8; w++) { t1 += sh1[w]; t2 += sh2[w]; }
        sh1[0] = t1; sh2[0] = t2;
    }
    __syncthreads();
    const float mu   = sh1[0] * (1.f/OUT_D);
    const float var  = sh2[0] * (1.f/OUT_D) - mu*mu;
    const float rstd = rsqrtf(var + 1e-5f);
    float* op = out + (size_t)row*OUT_D;
#pragma unroll
    for (int i = 0; i < 4; i++) {
        int c = tid + i*256;
        op[c] = (zg[i] - mu) * rstd + sk[i];
    }
}

/* ------------------------------------------------------------------ */
extern "C" void kernel_launch(void* const* d_in, const int* in_sizes, int n_in,
                              void* d_out, int out_size)
{
    (void)in_sizes; (void)n_in;
    const float* x      = (const float*)d_in[0];
    const float* st_re  = (const float*)d_in[1];
    const float* st_im  = (const float*)d_in[2];
    const unsigned char* start = (const unsigned char*)d_in[3];
    const float* pre_w  = (const float*)d_in[5];
    const float* pre_b  = (const float*)d_in[6];
    const float* gi_w   = (const float*)d_in[7];
    const float* gi_b   = (const float*)d_in[8];
    const float* go_w   = (const float*)d_in[9];
    const float* go_b   = (const float*)d_in[10];
    const float* skip_w = (const float*)d_in[11];
    const float* skip_b = (const float*)d_in[12];
    const float* mix_w  = (const float*)d_in[13];
    const float* mix_b  = (const float*)d_in[14];
    const float* ffa_a  = (const float*)d_in[15];
    const float* ffa_b  = (const float*)d_in[16];
    float* out = (float*)d_out;

    float *pzr, *pgs, *pfsd, *pbgs;
    __half *pxh, *pxl, *pzf, *pgsf, *pmxf, *pwch, *pwcl;
    cudaGetSymbolAddress((void**)&pzr,   g_zr);
    cudaGetSymbolAddress((void**)&pgs,   g_gs);
    cudaGetSymbolAddress((void**)&pfsd,  g_fsdump);
    cudaGetSymbolAddress((void**)&pbgs,  g_bgs);
    cudaGetSymbolAddress((void**)&pxh,   g_xh);
    cudaGetSymbolAddress((void**)&pxl,   g_xl);
    cudaGetSymbolAddress((void**)&pzf,   g_zf);
    cudaGetSymbolAddress((void**)&pgsf,  g_gsf);
    cudaGetSymbolAddress((void**)&pmxf,  g_mxf);
    cudaGetSymbolAddress((void**)&pwch,  g_wch);
    cudaGetSymbolAddress((void**)&pwcl,  g_wcl);

    /* final_state placement (proven in round 3): real-part-only pack  */
    const long base = (long)T_STEPS * OUT_D;                  /* 8388608 */
    const long osz  = (long)out_size;
    float* fs_dst  = pfsd;
    int    fs_mode = 0;
    if (osz == base + CH) {            /* 8389632: real-part-only pack */
        fs_dst  = out + base;
        fs_mode = 1;
    } else if (osz >= base + 2*CH) {
        fs_dst  = out + base;
        fs_mode = 0;
    } else if (2*osz >= base + 2*CH) {
        fs_dst  = out + base;
        fs_mode = 0;
    }

    /* one-time side-stream + events (same work on every call)         */
    static cudaStream_t s1 = nullptr;
    static cudaEvent_t  evFork = nullptr, evJoin = nullptr;
    if (s1 == nullptr) {
        cudaStreamCreateWithFlags(&s1, cudaStreamNonBlocking);
        cudaEventCreateWithFlags(&evFork, cudaEventDisableTiming);
        cudaEventCreateWithFlags(&evJoin, cudaEventDisableTiming);
        cudaFuncSetAttribute(hgemm_big,         cudaFuncAttributeMaxDynamicSharedMemorySize, BIG_SMEM);
        cudaFuncSetAttribute(hgemm_small_gated, cudaFuncAttributeMaxDynamicSharedMemorySize, SMALL_SMEM);
    }

    prep_start<<<1, 1024>>>(start);
    split_all<<<(CTq + 255)/256, 256>>>(x, gi_w, pre_w, go_w, skip_w, mix_w, go_b, skip_b);

    /* fork: go|skip GEMM depends only on split_all                    */
    cudaEventRecord(evFork, 0);
    cudaStreamWaitEvent(s1, evFork, 0);
    hgemm_big<<<dim3(T_STEPS/128, 2*OUT_D/128), 256, BIG_SMEM, s1>>>(
        pxh, pgsf, pbgs, pgs, 2*OUT_D, INPUT_D);
    cudaEventRecord(evJoin, s1);

    /* main stream: scan chain -> mix GEMM                             */
    hgemm_small_gated<<<T_STEPS/64, 256, SMALL_SMEM>>>(pxh, pxl, pwch, pwcl, gi_b, pre_b);
    scan_chunks <<<NCHUNK, 1024>>>(ffa_a, ffa_b);
    carry_kernel<<<1, 1024>>>(st_re, st_im, fs_dst, fs_mode);
    expand_kernel<<<NCHUNK, 1024>>>(ffa_a, ffa_b);
    hgemm_big<<<dim3(T_STEPS/128, OUT_D/128), 256, BIG_SMEM, 0>>>(
        pzf, pmxf, mix_b, pzr, OUT_D, 2*CH);

    /* join: ln needs both gs (s1) and zr (stream 0)                   */
    cudaStreamWaitEvent(0, evJoin, 0);
    ln_kernel<<<T_STEPS, 256>>>(out);
}

// round 10
// speedup vs baseline: 1.0269x; 1.0269x over previous
#include <cuda_runtime.h>
#include <cuda_fp16.h>
#include <stdint.h>

#define T_STEPS 8192
#define INPUT_D 1024
#define TRACE_D 64
#define CTX_D   16
#define OUT_D   1024
#define CH      (TRACE_D*CTX_D)      /* 1024 channels */
#define CHUNK   64
#define NCHUNK  (T_STEPS/CHUNK)      /* 128 */

/* ------------------------------------------------------------------ */
/* scratch (device globals: allocation-free rule)                      */
/* ------------------------------------------------------------------ */
__device__ float  g_gx[T_STEPS*TRACE_D];      /* gated_x                */
__device__ float2 g_Ac[NCHUNK*CH];
__device__ float2 g_Bc[NCHUNK*CH];
__device__ float2 g_carry[NCHUNK*CH];
__device__ float  g_zr [(size_t)T_STEPS*OUT_D];
__device__ float  g_gs [(size_t)T_STEPS*2*OUT_D];   /* go|skip fused, N=2048 */
__device__ unsigned char g_start[T_STEPS];
__device__ float  g_fsdump[2*CH];
__device__ float  g_bgs[2*OUT_D];             /* go_b | skip_b          */

/* fp16 operands for tensor-core GEMMs */
__device__ __half g_xh[(size_t)T_STEPS*INPUT_D];
__device__ __half g_xl[(size_t)T_STEPS*INPUT_D];
__device__ __half g_zf[(size_t)T_STEPS*2*CH];
__device__ __half g_gsf[2*OUT_D*INPUT_D];
__device__ __half g_mxf[OUT_D*2*CH];
__device__ __half g_wch[128*INPUT_D], g_wcl[128*INPUT_D];

/* ------------------------------------------------------------------ */
/* PTX helpers                                                         */
/* ------------------------------------------------------------------ */
__device__ __forceinline__ uint32_t smem_u32(const void* p){
    uint32_t a;
    asm("{ .reg .u64 t; cvta.to.shared.u64 t, %1; cvt.u32.u64 %0, t; }"
        : "=r"(a) : "l"(p));
    return a;
}
__device__ __forceinline__ void cpa16(uint32_t s, const void* g){
    asm volatile("cp.async.cg.shared.global [%0], [%1], 16;"
                 :: "r"(s), "l"(g) : "memory");
}
__device__ __forceinline__ void cpa_commit(){
    asm volatile("cp.async.commit_group;" ::: "memory");
}
template<int N>
__device__ __forceinline__ void cpa_wait(){
    asm volatile("cp.async.wait_group %0;" :: "n"(N) : "memory");
}
__device__ __forceinline__ void ldsm4(uint32_t* r, uint32_t a){
    asm volatile("ldmatrix.sync.aligned.m8n8.x4.shared.b16 {%0,%1,%2,%3}, [%4];"
                 : "=r"(r[0]), "=r"(r[1]), "=r"(r[2]), "=r"(r[3]) : "r"(a));
}
__device__ __forceinline__ void mma_f16(float* d, const uint32_t* a, const uint32_t* b){
    asm volatile(
        "mma.sync.aligned.m16n8k16.row.col.f32.f16.f16.f32 "
        "{%0,%1,%2,%3}, {%4,%5,%6,%7}, {%8,%9}, {%0,%1,%2,%3};"
        : "+f"(d[0]), "+f"(d[1]), "+f"(d[2]), "+f"(d[3])
        : "r"(a[0]), "r"(a[1]), "r"(a[2]), "r"(a[3]), "r"(b[0]), "r"(b[1]));
}
__device__ __forceinline__ uint32_t sw128(uint32_t b){
    return b ^ ((b >> 3) & 0x70);
}

#define DUAL_SMEM  (3*32768)                   /* 98304: 2 CTAs/SM      */
#define SMALL_SMEM (3*(2*8192 + 2*16384))      /* 147456                */

/* ------------------------------------------------------------------ */
/* DUAL big GEMM, fp16 single-pass, fp32 acc (proven 301us config).    */
/* job0 (bid<1024):  g_gs = xh @ gsf^T + bgs   (N=2048, K=1024)        */
/* job1 (bid>=1024): g_zr = zf @ mxf^T + mix_b (N=1024, K=2048)        */
/* ------------------------------------------------------------------ */
__global__ __launch_bounds__(256, 2)
void hgemm_dual(const __half* __restrict__ A0, const __half* __restrict__ W0,
                const float* __restrict__ b0, float* __restrict__ C0,
                const __half* __restrict__ A1, const __half* __restrict__ W1,
                const float* __restrict__ b1, float* __restrict__ C1)
{
    const int TSZ = 16384, STAGE = 32768;
    extern __shared__ char smem[];
    const uint32_t sb = smem_u32(smem);
    const int tid = threadIdx.x;
    const int wid = tid >> 5, l = tid & 31;

    const int bid  = blockIdx.x;
    const bool j1  = (bid >= 1024);
    const int lb   = j1 ? bid - 1024 : bid;
    const int bm   = (lb & 63) * 128;
    const int bn   = (lb >> 6) * 128;
    const int N    = j1 ? OUT_D : 2*OUT_D;
    const int K    = j1 ? 2*CH  : INPUT_D;
    const __half* A = j1 ? A1 : A0;
    const __half* W = j1 ? W1 : W0;
    const float* bias = j1 ? b1 : b0;
    float* C = j1 ? C1 : C0;

    const int wm0 = (wid & 3) * 32, wn0 = (wid >> 2) * 64;

    float acc[2][8][4];
#pragma unroll
    for (int mt = 0; mt < 2; mt++)
#pragma unroll
        for (int nt = 0; nt < 8; nt++)
#pragma unroll
            for (int j = 0; j < 4; j++) acc[mt][nt][j] = 0.f;

    const int nk = K >> 6;

    auto issue = [&](int s, int k0){
        const uint32_t st = sb + s * STAGE;
#pragma unroll
        for (int it = 0; it < 4; it++) {
            int idx = tid + it*256;
            int row = idx >> 3, cv = idx & 7;
            uint32_t sw = sw128((uint32_t)(row*128 + cv*16));
            cpa16(st +       sw, A + (size_t)(bm + row) * K + k0 + cv*8);
            cpa16(st + TSZ + sw, W + (size_t)(bn + row) * K + k0 + cv*8);
        }
        cpa_commit();
    };

    issue(0, 0);
    issue(1, 64);
    for (int kt = 0; kt < nk; kt++) {
        if (kt + 1 < nk) cpa_wait<1>(); else cpa_wait<0>();
        __syncthreads();
        if (kt + 2 < nk) issue((kt+2) % 3, (kt+2) << 6);

        const uint32_t st  = sb + (kt % 3) * STAGE;
        const uint32_t A_s = st, B_s = st + TSZ;

#pragma unroll
        for (int kk = 0; kk < 4; kk++) {
            uint32_t af[2][4];
#pragma unroll
            for (int mt = 0; mt < 2; mt++) {
                int row = wm0 + mt*16 + (l & 15);
                uint32_t sw = sw128((uint32_t)(row*128 + kk*32 + (l >> 4)*16));
                ldsm4(af[mt], A_s + sw);
            }
            uint32_t bf[4][4];
#pragma unroll
            for (int p = 0; p < 4; p++) {
                int row = wn0 + p*16 + ((l >> 4) & 1)*8 + (l & 7);
                uint32_t sw = sw128((uint32_t)(row*128 + kk*32 + ((l >> 3) & 1)*16));
                ldsm4(bf[p], B_s + sw);
            }
#pragma unroll
            for (int mt = 0; mt < 2; mt++)
#pragma unroll
                for (int nt = 0; nt < 8; nt++)
                    mma_f16(acc[mt][nt], af[mt], &bf[nt >> 1][(nt & 1)*2]);
        }
    }

#pragma unroll
    for (int mt = 0; mt < 2; mt++) {
        int row0 = bm + wm0 + mt*16 + (l >> 2);
#pragma unroll
        for (int nt = 0; nt < 8; nt++) {
            int col = bn + wn0 + nt*8 + (l & 3)*2;
            float bb0 = bias[col], bb1 = bias[col+1];
            float* c0 = C + (size_t)row0 * N + col;
            c0[0] = acc[mt][nt][0] + bb0;
            c0[1] = acc[mt][nt][1] + bb1;
            float* c1 = C + (size_t)(row0 + 8) * N + col;
            c1[0] = acc[mt][nt][2] + bb0;
            c1[1] = acc[mt][nt][3] + bb1;
        }
    }
}

/* ------------------------------------------------------------------ */
/* small GEMM (BM=64, N=128, K=1024), fp16 hi/lo 3-pass, with FUSED    */
/* gated epilogue AND fused scan phase-A: block j's 64 output rows     */
/* are exactly scan chunk j (CHUNK=64).                                */
/* ------------------------------------------------------------------ */
__global__ __launch_bounds__(256, 1)
void hgemm_small_gated(const __half* __restrict__ Ah, const __half* __restrict__ Al,
                       const __half* __restrict__ Wh, const __half* __restrict__ Wl,
                       const float* __restrict__ gi_b, const float* __restrict__ pre_b,
                       const float* __restrict__ ffa_a, const float* __restrict__ ffa_b)
{
    const int ASZ = 8192, STAGE = 2*ASZ + 2*16384, K = INPUT_D;
    extern __shared__ char smem[];
    const uint32_t sb = smem_u32(smem);
    const int tid = threadIdx.x;
    const int wid = tid >> 5, l = tid & 31;
    const int bm = blockIdx.x * 64;
    const int wm0 = (wid & 3) * 16, wn0 = (wid >> 2) * 64;
    const int lr = tid >> 3, lc = tid & 7;

    float acc[8][4];
#pragma unroll
    for (int nt = 0; nt < 8; nt++)
#pragma unroll
        for (int j = 0; j < 4; j++) acc[nt][j] = 0.f;

    const int nk = K >> 6;       /* 16 */

    auto issue = [&](int s, int k0){
        const uint32_t st = sb + s * STAGE;
#pragma unroll
        for (int it = 0; it < 2; it++) {
            int idx = tid + it*256;
            int row = idx >> 3, cv = idx & 7;
            uint32_t sw = sw128((uint32_t)(row*128 + cv*16));
            size_t ao = (size_t)(bm + row) * K + k0 + cv*8;
            cpa16(st +       sw, Ah + ao);
            cpa16(st + ASZ + sw, Al + ao);
        }
#pragma unroll
        for (int it = 0; it < 4; it++) {
            int row = lr + it*32, cv = lc;
            uint32_t sw = sw128((uint32_t)(row*128 + cv*16));
            size_t bo = (size_t)row * K + k0 + cv*8;
            cpa16(st + 2*ASZ +         sw, Wh + bo);
            cpa16(st + 2*ASZ + 16384 + sw, Wl + bo);
        }
        cpa_commit();
    };

    issue(0, 0);
    issue(1, 64);
    for (int kt = 0; kt < nk; kt++) {
        if (kt + 1 < nk) cpa_wait<1>(); else cpa_wait<0>();
        __syncthreads();
        if (kt + 2 < nk) issue((kt+2) % 3, (kt+2) << 6);

        const uint32_t st  = sb + (kt % 3) * STAGE;
        const uint32_t A_h = st, A_l = st + ASZ, B_h = st + 2*ASZ, B_l = st + 2*ASZ + 16384;

#pragma unroll
        for (int kk = 0; kk < 4; kk++) {
            uint32_t ah[4], al[4];
            {
                int row = wm0 + (l & 15);
                uint32_t sw = sw128((uint32_t)(row*128 + kk*32 + (l >> 4)*16));
                ldsm4(ah, A_h + sw);
                ldsm4(al, A_l + sw);
            }
            uint32_t bh[4][4], bl[4][4];
#pragma unroll
            for (int p = 0; p < 4; p++) {
                int row = wn0 + p*16 + ((l >> 4) & 1)*8 + (l & 7);
                uint32_t sw = sw128((uint32_t)(row*128 + kk*32 + ((l >> 3) & 1)*16));
                ldsm4(bh[p], B_h + sw);
                ldsm4(bl[p], B_l + sw);
            }
#pragma unroll
            for (int nt = 0; nt < 8; nt++) {
                const uint32_t* bhp = &bh[nt >> 1][(nt & 1)*2];
                const uint32_t* blp = &bl[nt >> 1][(nt & 1)*2];
                mma_f16(acc[nt], ah, bhp);
                mma_f16(acc[nt], ah, blp);
                mma_f16(acc[nt], al, bhp);
            }
        }
    }

    /* ---- fused epilogue 1: stage Y into smem --------------------- */
    __syncthreads();
    float* sY  = (float*)smem;                 /* [64][130]           */
    float* gxs = sY + 64*130;                  /* [64][65] gated_x    */
    unsigned char* ssm = (unsigned char*)(gxs + 64*65);
    const int YS = 130;
    {
        int row0 = wm0 + (l >> 2);
#pragma unroll
        for (int nt = 0; nt < 8; nt++) {
            int col = wn0 + nt*8 + (l & 3)*2;
            sY[row0*YS + col]     = acc[nt][0];
            sY[row0*YS + col + 1] = acc[nt][1];
            sY[(row0+8)*YS + col]     = acc[nt][2];
            sY[(row0+8)*YS + col + 1] = acc[nt][3];
        }
    }
    if (tid < 64) ssm[tid] = g_start[bm + tid];
    __syncthreads();

    /* ---- fused epilogue 2: gated_x -> gmem + smem ---------------- */
    const int m = tid & 63;
    const float gb = gi_b[m], pb = pre_b[m];
#pragma unroll
    for (int i = 0; i < 16; i++) {
        int r = (tid >> 6) + i*4;
        float y1 = sY[r*YS + m]      + gb;
        float y2 = sY[r*YS + 64 + m] + pb;
        float gx = y2 / (1.f + expf(-y1));
        g_gx[(size_t)(bm + r)*TRACE_D + m] = gx;
        gxs[r*65 + m] = gx;
    }
    __syncthreads();

    /* ---- fused epilogue 3: scan phase-A (4 channels/thread) ------ */
    float gr[4], gi_[4], Ar[4], Ai[4], Br[4], Bi[4];
    int mm[4];
#pragma unroll
    for (int q = 0; q < 4; q++) {
        int ch = tid + q*256;
        mm[q] = ch >> 4;
        int cc = ch & 15;
        float rr = expf(-fabsf(ffa_a[mm[q]]));
        gr[q] = rr * cosf(ffa_b[cc]);
        gi_[q] = rr * sinf(ffa_b[cc]);
        Ar[q] = 1.f; Ai[q] = 0.f; Br[q] = 0.f; Bi[q] = 0.f;
    }
#pragma unroll 2
    for (int t = 0; t < CHUNK; t++) {
        bool st = ssm[t];
#pragma unroll
        for (int q = 0; q < 4; q++) {
            float xv = gxs[t*65 + mm[q]];
            if (st) { Ar[q] = 0.f; Ai[q] = 0.f; Br[q] = xv; Bi[q] = 0.f; }
            else {
                float nAr = gr[q]*Ar[q] - gi_[q]*Ai[q];
                float nAi = gr[q]*Ai[q] + gi_[q]*Ar[q];
                float nBr = gr[q]*Br[q] - gi_[q]*Bi[q] + xv;
                float nBi = gr[q]*Bi[q] + gi_[q]*Br[q];
                Ar[q] = nAr; Ai[q] = nAi; Br[q] = nBr; Bi[q] = nBi;
            }
        }
    }
#pragma unroll
    for (int q = 0; q < 4; q++) {
        int ch = tid + q*256;
        g_Ac[blockIdx.x*CH + ch] = make_float2(Ar[q], Ai[q]);
        g_Bc[blockIdx.x*CH + ch] = make_float2(Br[q], Bi[q]);
    }
}

/* ------------------------------------------------------------------ */
/* merged conversion kernel                                            */
/* ------------------------------------------------------------------ */
#define XQ  2097152
#define WQ  16384
#define GQ  262144
#define MQ  524288
#define C1q (XQ)
#define C2q (C1q + WQ)
#define C3q (C2q + WQ)
#define C4q (C3q + GQ)
#define C5q (C4q + GQ)
#define C6q (C5q + MQ)
#define CTq (C6q + 512)

__device__ __forceinline__ void split_hl(const float4* __restrict__ s, long i,
                                         uint2* __restrict__ h, uint2* __restrict__ l)
{
    float4 v = s[i];
    __half h0 = __float2half(v.x), h1 = __float2half(v.y);
    __half h2 = __float2half(v.z), h3 = __float2half(v.w);
    __half l0 = __float2half(v.x - __half2float(h0));
    __half l1 = __float2half(v.y - __half2float(h1));
    __half l2 = __float2half(v.z - __half2float(h2));
    __half l3 = __float2half(v.w - __half2float(h3));
    uint2 uh, ul;
    uh.x = (uint32_t)__half_as_ushort(h0) | ((uint32_t)__half_as_ushort(h1) << 16);
    uh.y = (uint32_t)__half_as_ushort(h2) | ((uint32_t)__half_as_ushort(h3) << 16);
    ul.x = (uint32_t)__half_as_ushort(l0) | ((uint32_t)__half_as_ushort(l1) << 16);
    ul.y = (uint32_t)__half_as_ushort(l2) | ((uint32_t)__half_as_ushort(l3) << 16);
    h[i] = uh; l[i] = ul;
}
__device__ __forceinline__ void cvt_h(const float4* __restrict__ s, long i,
                                      uint2* __restrict__ o)
{
    float4 v = s[i];
    uint2 u;
    u.x = (uint32_t)__half_as_ushort(__float2half(v.x))
        | ((uint32_t)__half_as_ushort(__float2half(v.y)) << 16);
    u.y = (uint32_t)__half_as_ushort(__float2half(v.z))
        | ((uint32_t)__half_as_ushort(__float2half(v.w)) << 16);
    o[i] = u;
}

__global__ void split_all(const float* __restrict__ x,
                          const float* __restrict__ gi_w, const float* __restrict__ pre_w,
                          const float* __restrict__ go_w, const float* __restrict__ skip_w,
                          const float* __restrict__ mix_w,
                          const float* __restrict__ go_b, const float* __restrict__ skip_b)
{
    long i = (long)blockIdx.x * blockDim.x + threadIdx.x;
    if (i >= CTq) return;
    if (i < C1q)      split_hl((const float4*)x,     i,       (uint2*)g_xh,  (uint2*)g_xl);
    else if (i < C2q) split_hl((const float4*)gi_w,  i - C1q, (uint2*)g_wch, (uint2*)g_wcl);
    else if (i < C3q) split_hl((const float4*)pre_w, i - C2q,
                               (uint2*)(g_wch + 64*INPUT_D), (uint2*)(g_wcl + 64*INPUT_D));
    else if (i < C4q) cvt_h((const float4*)go_w,   i - C3q, (uint2*)g_gsf);
    else if (i < C5q) cvt_h((const float4*)skip_w, i - C4q,
                            (uint2*)(g_gsf + (size_t)OUT_D*INPUT_D));
    else if (i < C6q) cvt_h((const float4*)mix_w,  i - C5q, (uint2*)g_mxf);
    else {
        long i2 = i - C6q;
        float4 v = (i2 < 256) ? ((const float4*)go_b)[i2] : ((const float4*)skip_b)[i2 - 256];
        ((float4*)g_bgs)[i2] = v;
    }
}

/* ------------------------------------------------------------------ */
/* start-flag canonicalization, single block                           */
/* ------------------------------------------------------------------ */
__global__ __launch_bounds__(1024)
void prep_start(const unsigned char* __restrict__ s8)
{
    __shared__ int flags[3];
    const int tid = threadIdx.x;
    if (tid < 3) flags[tid] = 0;
    __syncthreads();
    const unsigned int* s32 = (const unsigned int*)s8;
    for (int i = tid; i < 2048; i += 1024) {
        unsigned v = s32[i];
        if (v == 0u) continue;
        else if (v == 1u)           atomicOr(&flags[0], 1);
        else if (v == 0x3f800000u)  atomicOr(&flags[1], 1);
        else                        atomicOr(&flags[2], 1);
    }
    __syncthreads();
    const int mode = flags[2] ? 0 : (flags[1] ? 2 : (flags[0] ? 1 : 0));
#pragma unroll
    for (int i = 0; i < 8; i++) {
        int idx = tid + i*1024;
        unsigned char v;
        if (mode == 1)      v = (((const int*)  s8)[idx] != 0);
        else if (mode == 2) v = (((const float*)s8)[idx] != 0.f);
        else                v = (s8[idx] != 0);
        g_start[idx] = v;
    }
}

/* Phase B: sequential carry over 128 chunks; emits final_state.       */
__global__ __launch_bounds__(1024)
void carry_kernel(const float* __restrict__ st_re, const float* __restrict__ st_im,
                  float* __restrict__ out_fs, int fs_mode)
{
    const int tid = threadIdx.x;
    float sr = st_re[tid], si = st_im[tid];
    for (int j0 = 0; j0 < NCHUNK; j0 += 8) {
        float2 a[8], b[8];
#pragma unroll
        for (int u = 0; u < 8; u++) { a[u] = g_Ac[(j0+u)*CH + tid]; b[u] = g_Bc[(j0+u)*CH + tid]; }
#pragma unroll
        for (int u = 0; u < 8; u++) {
            g_carry[(j0+u)*CH + tid] = make_float2(sr, si);
            float nr = a[u].x*sr - a[u].y*si + b[u].x;
            float ni = a[u].x*si + a[u].y*sr + b[u].y;
            sr = nr; si = ni;
        }
    }
    if (fs_mode == 1) {
        out_fs[tid] = sr;
    } else {
        out_fs[2*tid]   = sr;
        out_fs[2*tid+1] = si;
    }
}

/* Phase C: replay chunks; write z_in fp16 [T, 2048]                   */
__global__ __launch_bounds__(1024)
void expand_kernel(const float* __restrict__ ffa_a, const float* __restrict__ ffa_b)
{
    __shared__ float sx[CHUNK*TRACE_D];
    __shared__ unsigned char ss[CHUNK];
    const int chunk = blockIdx.x, tid = threadIdx.x;
    const float* src = g_gx + chunk*CHUNK*TRACE_D;
    for (int i = tid; i < CHUNK*TRACE_D; i += 1024) sx[i] = src[i];
    if (tid < CHUNK) ss[tid] = g_start[chunk*CHUNK + tid];
    __syncthreads();

    const int m = tid >> 4, c = tid & 15;
    const float r  = expf(-fabsf(ffa_a[m]));
    const float gr = r * cosf(ffa_b[c]);
    const float gi = r * sinf(ffa_b[c]);

    float2 s = g_carry[chunk*CH + tid];
    const size_t zo = (size_t)chunk*CHUNK*2*CH + m*32 + c;
#pragma unroll 2
    for (int t = 0; t < CHUNK; t++) {
        float xv = sx[t*TRACE_D + m];
        float nr, ni;
        if (ss[t]) { nr = xv; ni = 0.f; }
        else { nr = gr*s.x - gi*s.y + xv; ni = gr*s.y + gi*s.x; }
        s.x = nr; s.y = ni;
        size_t o = zo + (size_t)t*2048;
        g_zf[o]      = __float2half(nr);
        g_zf[o + 16] = __float2half(ni);
    }
}

/* ------------------------------------------------------------------ */
/* epilogue: zg = z*sig(go); LN(zg) + skip*(1-sig(go))                 */
/* ------------------------------------------------------------------ */
__global__ __launch_bounds__(256)
void ln_kernel(float* __restrict__ out)
{
    const int row = blockIdx.x, tid = threadIdx.x;
    const float* zp = g_zr + (size_t)row*OUT_D;
    const float* gp = g_gs + (size_t)row*2*OUT_D;
    const float* sp = gp + OUT_D;

    float zg[4], sk[4], s1 = 0.f, s2 = 0.f;
#pragma unroll
    for (int i = 0; i < 4; i++) {
        int c = tid + i*256;
        float g  = 1.f / (1.f + expf(-gp[c]));
        float zv = zp[c] * g;
        zg[i] = zv; s1 += zv; s2 += zv*zv;
        sk[i] = sp[c] * (1.f - g);
    }
#pragma unroll
    for (int o = 16; o > 0; o >>= 1) {
        s1 += __shfl_xor_sync(0xffffffffu, s1, o);
        s2 += __shfl_xor_sync(0xffffffffu, s2, o);
    }
    __shared__ float sh1[8], sh2[8];
    const int warp = tid >> 5, lane = tid & 31;
    if (lane == 0) { sh1[warp] = s1; sh2[warp] = s2; }
    __syncthreads();
    if (tid == 0) {
        float t1 = 0.f, t2 = 0.f;
        for (int w = 0; w < 8; w++) { t1 += sh1[w]; t2 += sh2[w]; }
        sh1[0] = t1; sh2[0] = t2;
    }
    __syncthreads();
    const float mu   = sh1[0] * (1.f/OUT_D);
    const float var  = sh2[0] * (1.f/OUT_D) - mu*mu;
    const float rstd = rsqrtf(var + 1e-5f);
    float* op = out + (size_t)row*OUT_D;
#pragma unroll
    for (int i = 0; i < 4; i++) {
        int c = tid + i*256;
        op[c] = (zg[i] - mu) * rstd + sk[i];
    }
}

/* ------------------------------------------------------------------ */
extern "C" void kernel_launch(void* const* d_in, const int* in_sizes, int n_in,
                              void* d_out, int out_size)
{
    (void)in_sizes; (void)n_in;
    const float* x      = (const float*)d_in[0];
    const float* st_re  = (const float*)d_in[1];
    const float* st_im  = (const float*)d_in[2];
    const unsigned char* start = (const unsigned char*)d_in[3];
    const float* pre_w  = (const float*)d_in[5];
    const float* pre_b  = (const float*)d_in[6];
    const float* gi_w   = (const float*)d_in[7];
    const float* gi_b   = (const float*)d_in[8];
    const float* go_w   = (const float*)d_in[9];
    const float* go_b   = (const float*)d_in[10];
    const float* skip_w = (const float*)d_in[11];
    const float* skip_b = (const float*)d_in[12];
    const float* mix_w  = (const float*)d_in[13];
    const float* mix_b  = (const float*)d_in[14];
    const float* ffa_a  = (const float*)d_in[15];
    const float* ffa_b  = (const float*)d_in[16];
    float* out = (float*)d_out;

    float *pzr, *pgs, *pfsd, *pbgs;
    __half *pxh, *pxl, *pzf, *pgsf, *pmxf, *pwch, *pwcl;
    cudaGetSymbolAddress((void**)&pzr,   g_zr);
    cudaGetSymbolAddress((void**)&pgs,   g_gs);
    cudaGetSymbolAddress((void**)&pfsd,  g_fsdump);
    cudaGetSymbolAddress((void**)&pbgs,  g_bgs);
    cudaGetSymbolAddress((void**)&pxh,   g_xh);
    cudaGetSymbolAddress((void**)&pxl,   g_xl);
    cudaGetSymbolAddress((void**)&pzf,   g_zf);
    cudaGetSymbolAddress((void**)&pgsf,  g_gsf);
    cudaGetSymbolAddress((void**)&pmxf,  g_mxf);
    cudaGetSymbolAddress((void**)&pwch,  g_wch);
    cudaGetSymbolAddress((void**)&pwcl,  g_wcl);

    /* final_state placement (proven in round 3): real-part-only pack  */
    const long base = (long)T_STEPS * OUT_D;                  /* 8388608 */
    const long osz  = (long)out_size;
    float* fs_dst  = pfsd;
    int    fs_mode = 0;
    if (osz == base + CH) {            /* 8389632: real-part-only pack */
        fs_dst  = out + base;
        fs_mode = 1;
    } else if (osz >= base + 2*CH) {
        fs_dst  = out + base;
        fs_mode = 0;
    } else if (2*osz >= base + 2*CH) {
        fs_dst  = out + base;
        fs_mode = 0;
    }

    static int inited = 0;
    if (!inited) {
        cudaFuncSetAttribute(hgemm_dual,        cudaFuncAttributeMaxDynamicSharedMemorySize, DUAL_SMEM);
        cudaFuncSetAttribute(hgemm_small_gated, cudaFuncAttributeMaxDynamicSharedMemorySize, SMALL_SMEM);
        inited = 1;
    }

    prep_start<<<1, 1024>>>(start);
    split_all<<<(CTq + 255)/256, 256>>>(x, gi_w, pre_w, go_w, skip_w, mix_w, go_b, skip_b);

    /* small GEMM + gated + scan-A fused (block j == chunk j)          */
    hgemm_small_gated<<<T_STEPS/64, 256, SMALL_SMEM>>>(pxh, pxl, pwch, pwcl,
                                                       gi_b, pre_b, ffa_a, ffa_b);
    carry_kernel<<<1, 1024>>>(st_re, st_im, fs_dst, fs_mode);
    expand_kernel<<<NCHUNK, 1024>>>(ffa_a, ffa_b);

    hgemm_dual<<<1536, 256, DUAL_SMEM>>>(pxh, pgsf, pbgs, pgs,
                                         pzf, pmxf, mix_b, pzr);

    ln_kernel<<<T_STEPS, 256>>>(out);
}

// round 11
// speedup vs baseline: 1.0936x; 1.0650x over previous
#include <cuda_runtime.h>
#include <cuda_fp16.h>
#include <stdint.h>

#define T_STEPS 8192
#define INPUT_D 1024
#define TRACE_D 64
#define CTX_D   16
#define OUT_D   1024
#define CH      (TRACE_D*CTX_D)      /* 1024 channels */
#define CHUNK   64
#define NCHUNK  (T_STEPS/CHUNK)      /* 128 */

/* ------------------------------------------------------------------ */
/* scratch (device globals: allocation-free rule)                      */
/* ------------------------------------------------------------------ */
__device__ float  g_gx[T_STEPS*TRACE_D];      /* gated_x                */
__device__ float2 g_Ac[NCHUNK*CH];
__device__ float2 g_Bc[NCHUNK*CH];
__device__ float2 g_carry[NCHUNK*CH];
__device__ float  g_zr [(size_t)T_STEPS*OUT_D];
__device__ float  g_gs [(size_t)T_STEPS*2*OUT_D];   /* go|skip fused, N=2048 */
__device__ unsigned char g_start[T_STEPS];
__device__ float  g_fsdump[2*CH];
__device__ float  g_bgs[2*OUT_D];             /* go_b | skip_b          */

/* fp16 operands for tensor-core GEMMs */
__device__ __half g_xh[(size_t)T_STEPS*INPUT_D];
__device__ __half g_xl[(size_t)T_STEPS*INPUT_D];
__device__ __half g_zf[(size_t)T_STEPS*2*CH];
__device__ __half g_gsf[2*OUT_D*INPUT_D];
__device__ __half g_mxf[OUT_D*2*CH];
__device__ __half g_wch[128*INPUT_D], g_wcl[128*INPUT_D];

/* ------------------------------------------------------------------ */
/* PTX helpers                                                         */
/* ------------------------------------------------------------------ */
__device__ __forceinline__ uint32_t smem_u32(const void* p){
    uint32_t a;
    asm("{ .reg .u64 t; cvta.to.shared.u64 t, %1; cvt.u32.u64 %0, t; }"
        : "=r"(a) : "l"(p));
    return a;
}
__device__ __forceinline__ void cpa16(uint32_t s, const void* g){
    asm volatile("cp.async.cg.shared.global [%0], [%1], 16;"
                 :: "r"(s), "l"(g) : "memory");
}
__device__ __forceinline__ void cpa_commit(){
    asm volatile("cp.async.commit_group;" ::: "memory");
}
template<int N>
__device__ __forceinline__ void cpa_wait(){
    asm volatile("cp.async.wait_group %0;" :: "n"(N) : "memory");
}
__device__ __forceinline__ void ldsm4(uint32_t* r, uint32_t a){
    asm volatile("ldmatrix.sync.aligned.m8n8.x4.shared.b16 {%0,%1,%2,%3}, [%4];"
                 : "=r"(r[0]), "=r"(r[1]), "=r"(r[2]), "=r"(r[3]) : "r"(a));
}
__device__ __forceinline__ void mma_f16(float* d, const uint32_t* a, const uint32_t* b){
    asm volatile(
        "mma.sync.aligned.m16n8k16.row.col.f32.f16.f16.f32 "
        "{%0,%1,%2,%3}, {%4,%5,%6,%7}, {%8,%9}, {%0,%1,%2,%3};"
        : "+f"(d[0]), "+f"(d[1]), "+f"(d[2]), "+f"(d[3])
        : "r"(a[0]), "r"(a[1]), "r"(a[2]), "r"(a[3]), "r"(b[0]), "r"(b[1]));
}
__device__ __forceinline__ uint32_t sw128(uint32_t b){
    return b ^ ((b >> 3) & 0x70);
}

#define DUAL_SMEM  (3*32768)                   /* 98304: 2 CTAs/SM      */
#define SMALL_SMEM (3*(2*8192 + 2*16384))      /* 147456                */

/* ------------------------------------------------------------------ */
/* DUAL big GEMM, fp16 single-pass, fp32 acc (proven 301us config).    */
/* job0 (bid<1024):  g_gs = xh @ gsf^T + bgs   (N=2048, K=1024)        */
/* job1 (bid>=1024): g_zr = zf @ mxf^T + mix_b (N=1024, K=2048)        */
/* ------------------------------------------------------------------ */
__global__ __launch_bounds__(256, 2)
void hgemm_dual(const __half* __restrict__ A0, const __half* __restrict__ W0,
                const float* __restrict__ b0, float* __restrict__ C0,
                const __half* __restrict__ A1, const __half* __restrict__ W1,
                const float* __restrict__ b1, float* __restrict__ C1)
{
    const int TSZ = 16384, STAGE = 32768;
    extern __shared__ char smem[];
    const uint32_t sb = smem_u32(smem);
    const int tid = threadIdx.x;
    const int wid = tid >> 5, l = tid & 31;

    const int bid  = blockIdx.x;
    const bool j1  = (bid >= 1024);
    const int lb   = j1 ? bid - 1024 : bid;
    const int bm   = (lb & 63) * 128;
    const int bn   = (lb >> 6) * 128;
    const int N    = j1 ? OUT_D : 2*OUT_D;
    const int K    = j1 ? 2*CH  : INPUT_D;
    const __half* A = j1 ? A1 : A0;
    const __half* W = j1 ? W1 : W0;
    const float* bias = j1 ? b1 : b0;
    float* C = j1 ? C1 : C0;

    const int wm0 = (wid & 3) * 32, wn0 = (wid >> 2) * 64;

    float acc[2][8][4];
#pragma unroll
    for (int mt = 0; mt < 2; mt++)
#pragma unroll
        for (int nt = 0; nt < 8; nt++)
#pragma unroll
            for (int j = 0; j < 4; j++) acc[mt][nt][j] = 0.f;

    const int nk = K >> 6;

    auto issue = [&](int s, int k0){
        const uint32_t st = sb + s * STAGE;
#pragma unroll
        for (int it = 0; it < 4; it++) {
            int idx = tid + it*256;
            int row = idx >> 3, cv = idx & 7;
            uint32_t sw = sw128((uint32_t)(row*128 + cv*16));
            cpa16(st +       sw, A + (size_t)(bm + row) * K + k0 + cv*8);
            cpa16(st + TSZ + sw, W + (size_t)(bn + row) * K + k0 + cv*8);
        }
        cpa_commit();
    };

    issue(0, 0);
    issue(1, 64);
    for (int kt = 0; kt < nk; kt++) {
        if (kt + 1 < nk) cpa_wait<1>(); else cpa_wait<0>();
        __syncthreads();
        if (kt + 2 < nk) issue((kt+2) % 3, (kt+2) << 6);

        const uint32_t st  = sb + (kt % 3) * STAGE;
        const uint32_t A_s = st, B_s = st + TSZ;

#pragma unroll
        for (int kk = 0; kk < 4; kk++) {
            uint32_t af[2][4];
#pragma unroll
            for (int mt = 0; mt < 2; mt++) {
                int row = wm0 + mt*16 + (l & 15);
                uint32_t sw = sw128((uint32_t)(row*128 + kk*32 + (l >> 4)*16));
                ldsm4(af[mt], A_s + sw);
            }
            uint32_t bf[4][4];
#pragma unroll
            for (int p = 0; p < 4; p++) {
                int row = wn0 + p*16 + ((l >> 4) & 1)*8 + (l & 7);
                uint32_t sw = sw128((uint32_t)(row*128 + kk*32 + ((l >> 3) & 1)*16));
                ldsm4(bf[p], B_s + sw);
            }
#pragma unroll
            for (int mt = 0; mt < 2; mt++)
#pragma unroll
                for (int nt = 0; nt < 8; nt++)
                    mma_f16(acc[mt][nt], af[mt], &bf[nt >> 1][(nt & 1)*2]);
        }
    }

#pragma unroll
    for (int mt = 0; mt < 2; mt++) {
        int row0 = bm + wm0 + mt*16 + (l >> 2);
#pragma unroll
        for (int nt = 0; nt < 8; nt++) {
            int col = bn + wn0 + nt*8 + (l & 3)*2;
            float bb0 = bias[col], bb1 = bias[col+1];
            float* c0 = C + (size_t)row0 * N + col;
            c0[0] = acc[mt][nt][0] + bb0;
            c0[1] = acc[mt][nt][1] + bb1;
            float* c1 = C + (size_t)(row0 + 8) * N + col;
            c1[0] = acc[mt][nt][2] + bb0;
            c1[1] = acc[mt][nt][3] + bb1;
        }
    }
}

/* ------------------------------------------------------------------ */
/* small GEMM (BM=64, N=128, K=1024), fp16 hi/lo 3-pass, with FUSED    */
/* gated epilogue AND fused scan phase-A (block j == chunk j).         */
/* ------------------------------------------------------------------ */
__global__ __launch_bounds__(256, 1)
void hgemm_small_gated(const __half* __restrict__ Ah, const __half* __restrict__ Al,
                       const __half* __restrict__ Wh, const __half* __restrict__ Wl,
                       const float* __restrict__ gi_b, const float* __restrict__ pre_b,
                       const float* __restrict__ ffa_a, const float* __restrict__ ffa_b)
{
    const int ASZ = 8192, STAGE = 2*ASZ + 2*16384, K = INPUT_D;
    extern __shared__ char smem[];
    const uint32_t sb = smem_u32(smem);
    const int tid = threadIdx.x;
    const int wid = tid >> 5, l = tid & 31;
    const int bm = blockIdx.x * 64;
    const int wm0 = (wid & 3) * 16, wn0 = (wid >> 2) * 64;
    const int lr = tid >> 3, lc = tid & 7;

    float acc[8][4];
#pragma unroll
    for (int nt = 0; nt < 8; nt++)
#pragma unroll
        for (int j = 0; j < 4; j++) acc[nt][j] = 0.f;

    const int nk = K >> 6;       /* 16 */

    auto issue = [&](int s, int k0){
        const uint32_t st = sb + s * STAGE;
#pragma unroll
        for (int it = 0; it < 2; it++) {
            int idx = tid + it*256;
            int row = idx >> 3, cv = idx & 7;
            uint32_t sw = sw128((uint32_t)(row*128 + cv*16));
            size_t ao = (size_t)(bm + row) * K + k0 + cv*8;
            cpa16(st +       sw, Ah + ao);
            cpa16(st + ASZ + sw, Al + ao);
        }
#pragma unroll
        for (int it = 0; it < 4; it++) {
            int row = lr + it*32, cv = lc;
            uint32_t sw = sw128((uint32_t)(row*128 + cv*16));
            size_t bo = (size_t)row * K + k0 + cv*8;
            cpa16(st + 2*ASZ +         sw, Wh + bo);
            cpa16(st + 2*ASZ + 16384 + sw, Wl + bo);
        }
        cpa_commit();
    };

    issue(0, 0);
    issue(1, 64);
    for (int kt = 0; kt < nk; kt++) {
        if (kt + 1 < nk) cpa_wait<1>(); else cpa_wait<0>();
        __syncthreads();
        if (kt + 2 < nk) issue((kt+2) % 3, (kt+2) << 6);

        const uint32_t st  = sb + (kt % 3) * STAGE;
        const uint32_t A_h = st, A_l = st + ASZ, B_h = st + 2*ASZ, B_l = st + 2*ASZ + 16384;

#pragma unroll
        for (int kk = 0; kk < 4; kk++) {
            uint32_t ah[4], al[4];
            {
                int row = wm0 + (l & 15);
                uint32_t sw = sw128((uint32_t)(row*128 + kk*32 + (l >> 4)*16));
                ldsm4(ah, A_h + sw);
                ldsm4(al, A_l + sw);
            }
            uint32_t bh[4][4], bl[4][4];
#pragma unroll
            for (int p = 0; p < 4; p++) {
                int row = wn0 + p*16 + ((l >> 4) & 1)*8 + (l & 7);
                uint32_t sw = sw128((uint32_t)(row*128 + kk*32 + ((l >> 3) & 1)*16));
                ldsm4(bh[p], B_h + sw);
                ldsm4(bl[p], B_l + sw);
            }
#pragma unroll
            for (int nt = 0; nt < 8; nt++) {
                const uint32_t* bhp = &bh[nt >> 1][(nt & 1)*2];
                const uint32_t* blp = &bl[nt >> 1][(nt & 1)*2];
                mma_f16(acc[nt], ah, bhp);
                mma_f16(acc[nt], ah, blp);
                mma_f16(acc[nt], al, bhp);
            }
        }
    }

    /* ---- fused epilogue 1: stage Y into smem --------------------- */
    __syncthreads();
    float* sY  = (float*)smem;                 /* [64][130]           */
    float* gxs = sY + 64*130;                  /* [64][65] gated_x    */
    unsigned char* ssm = (unsigned char*)(gxs + 64*65);
    const int YS = 130;
    {
        int row0 = wm0 + (l >> 2);
#pragma unroll
        for (int nt = 0; nt < 8; nt++) {
            int col = wn0 + nt*8 + (l & 3)*2;
            sY[row0*YS + col]     = acc[nt][0];
            sY[row0*YS + col + 1] = acc[nt][1];
            sY[(row0+8)*YS + col]     = acc[nt][2];
            sY[(row0+8)*YS + col + 1] = acc[nt][3];
        }
    }
    if (tid < 64) ssm[tid] = g_start[bm + tid];
    __syncthreads();

    /* ---- fused epilogue 2: gated_x -> gmem + smem ---------------- */
    const int m = tid & 63;
    const float gb = gi_b[m], pb = pre_b[m];
#pragma unroll
    for (int i = 0; i < 16; i++) {
        int r = (tid >> 6) + i*4;
        float y1 = sY[r*YS + m]      + gb;
        float y2 = sY[r*YS + 64 + m] + pb;
        float gx = y2 / (1.f + expf(-y1));
        g_gx[(size_t)(bm + r)*TRACE_D + m] = gx;
        gxs[r*65 + m] = gx;
    }
    __syncthreads();

    /* ---- fused epilogue 3: scan phase-A (4 channels/thread) ------ */
    float gr[4], gi_[4], Ar[4], Ai[4], Br[4], Bi[4];
    int mm[4];
#pragma unroll
    for (int q = 0; q < 4; q++) {
        int ch = tid + q*256;
        mm[q] = ch >> 4;
        int cc = ch & 15;
        float rr = expf(-fabsf(ffa_a[mm[q]]));
        gr[q] = rr * cosf(ffa_b[cc]);
        gi_[q] = rr * sinf(ffa_b[cc]);
        Ar[q] = 1.f; Ai[q] = 0.f; Br[q] = 0.f; Bi[q] = 0.f;
    }
#pragma unroll 2
    for (int t = 0; t < CHUNK; t++) {
        bool st = ssm[t];
#pragma unroll
        for (int q = 0; q < 4; q++) {
            float xv = gxs[t*65 + mm[q]];
            if (st) { Ar[q] = 0.f; Ai[q] = 0.f; Br[q] = xv; Bi[q] = 0.f; }
            else {
                float nAr = gr[q]*Ar[q] - gi_[q]*Ai[q];
                float nAi = gr[q]*Ai[q] + gi_[q]*Ar[q];
                float nBr = gr[q]*Br[q] - gi_[q]*Bi[q] + xv;
                float nBi = gr[q]*Bi[q] + gi_[q]*Br[q];
                Ar[q] = nAr; Ai[q] = nAi; Br[q] = nBr; Bi[q] = nBi;
            }
        }
    }
#pragma unroll
    for (int q = 0; q < 4; q++) {
        int ch = tid + q*256;
        g_Ac[blockIdx.x*CH + ch] = make_float2(Ar[q], Ai[q]);
        g_Bc[blockIdx.x*CH + ch] = make_float2(Br[q], Bi[q]);
    }
}

/* ------------------------------------------------------------------ */
/* merged conversion kernel                                            */
/* ------------------------------------------------------------------ */
#define XQ  2097152
#define WQ  16384
#define GQ  262144
#define MQ  524288
#define C1q (XQ)
#define C2q (C1q + WQ)
#define C3q (C2q + WQ)
#define C4q (C3q + GQ)
#define C5q (C4q + GQ)
#define C6q (C5q + MQ)
#define CTq (C6q + 512)

__device__ __forceinline__ void split_hl(const float4* __restrict__ s, long i,
                                         uint2* __restrict__ h, uint2* __restrict__ l)
{
    float4 v = s[i];
    __half h0 = __float2half(v.x), h1 = __float2half(v.y);
    __half h2 = __float2half(v.z), h3 = __float2half(v.w);
    __half l0 = __float2half(v.x - __half2float(h0));
    __half l1 = __float2half(v.y - __half2float(h1));
    __half l2 = __float2half(v.z - __half2float(h2));
    __half l3 = __float2half(v.w - __half2float(h3));
    uint2 uh, ul;
    uh.x = (uint32_t)__half_as_ushort(h0) | ((uint32_t)__half_as_ushort(h1) << 16);
    uh.y = (uint32_t)__half_as_ushort(h2) | ((uint32_t)__half_as_ushort(h3) << 16);
    ul.x = (uint32_t)__half_as_ushort(l0) | ((uint32_t)__half_as_ushort(l1) << 16);
    ul.y = (uint32_t)__half_as_ushort(l2) | ((uint32_t)__half_as_ushort(l3) << 16);
    h[i] = uh; l[i] = ul;
}
__device__ __forceinline__ void cvt_h(const float4* __restrict__ s, long i,
                                      uint2* __restrict__ o)
{
    float4 v = s[i];
    uint2 u;
    u.x = (uint32_t)__half_as_ushort(__float2half(v.x))
        | ((uint32_t)__half_as_ushort(__float2half(v.y)) << 16);
    u.y = (uint32_t)__half_as_ushort(__float2half(v.z))
        | ((uint32_t)__half_as_ushort(__float2half(v.w)) << 16);
    o[i] = u;
}

__global__ void split_all(const float* __restrict__ x,
                          const float* __restrict__ gi_w, const float* __restrict__ pre_w,
                          const float* __restrict__ go_w, const float* __restrict__ skip_w,
                          const float* __restrict__ mix_w,
                          const float* __restrict__ go_b, const float* __restrict__ skip_b)
{
    long i = (long)blockIdx.x * blockDim.x + threadIdx.x;
    if (i >= CTq) return;
    if (i < C1q)      split_hl((const float4*)x,     i,       (uint2*)g_xh,  (uint2*)g_xl);
    else if (i < C2q) split_hl((const float4*)gi_w,  i - C1q, (uint2*)g_wch, (uint2*)g_wcl);
    else if (i < C3q) split_hl((const float4*)pre_w, i - C2q,
                               (uint2*)(g_wch + 64*INPUT_D), (uint2*)(g_wcl + 64*INPUT_D));
    else if (i < C4q) cvt_h((const float4*)go_w,   i - C3q, (uint2*)g_gsf);
    else if (i < C5q) cvt_h((const float4*)skip_w, i - C4q,
                            (uint2*)(g_gsf + (size_t)OUT_D*INPUT_D));
    else if (i < C6q) cvt_h((const float4*)mix_w,  i - C5q, (uint2*)g_mxf);
    else {
        long i2 = i - C6q;
        float4 v = (i2 < 256) ? ((const float4*)go_b)[i2] : ((const float4*)skip_b)[i2 - 256];
        ((float4*)g_bgs)[i2] = v;
    }
}

/* ------------------------------------------------------------------ */
/* start-flag canonicalization, single block                           */
/* ------------------------------------------------------------------ */
__global__ __launch_bounds__(1024)
void prep_start(const unsigned char* __restrict__ s8)
{
    __shared__ int flags[3];
    const int tid = threadIdx.x;
    if (tid < 3) flags[tid] = 0;
    __syncthreads();
    const unsigned int* s32 = (const unsigned int*)s8;
    for (int i = tid; i < 2048; i += 1024) {
        unsigned v = s32[i];
        if (v == 0u) continue;
        else if (v == 1u)           atomicOr(&flags[0], 1);
        else if (v == 0x3f800000u)  atomicOr(&flags[1], 1);
        else                        atomicOr(&flags[2], 1);
    }
    __syncthreads();
    const int mode = flags[2] ? 0 : (flags[1] ? 2 : (flags[0] ? 1 : 0));
#pragma unroll
    for (int i = 0; i < 8; i++) {
        int idx = tid + i*1024;
        unsigned char v;
        if (mode == 1)      v = (((const int*)  s8)[idx] != 0);
        else if (mode == 2) v = (((const float*)s8)[idx] != 0.f);
        else                v = (s8[idx] != 0);
        g_start[idx] = v;
    }
}

/* ------------------------------------------------------------------ */
/* Phase B: PARALLEL warp-scan carry. 1 warp per channel; lane owns    */
/* 4 consecutive chunks. Kogge-Stone inclusive scan of affine maps     */
/* (A,B) over lanes, shifted to exclusive, applied to s0. Emits        */
/* per-chunk carries and final_state. grid=32, block=1024.             */
/* ------------------------------------------------------------------ */
__global__ __launch_bounds__(1024)
void carry_scan(const float* __restrict__ st_re, const float* __restrict__ st_im,
                float* __restrict__ out_fs, int fs_mode)
{
    const int tid  = threadIdx.x;
    const int wid  = tid >> 5, lane = tid & 31;
    const int ch   = blockIdx.x * 32 + wid;          /* 0..1023 */
    const unsigned FULL = 0xffffffffu;

    /* load 4 chunk affines, compose serially: f = f3∘f2∘f1∘f0        */
    float2 a[4], b[4];
#pragma unroll
    for (int u = 0; u < 4; u++) {
        int j = lane*4 + u;
        a[u] = g_Ac[j*CH + ch];
        b[u] = g_Bc[j*CH + ch];
    }
    float Atr = a[0].x, Ati = a[0].y, Btr = b[0].x, Bti = b[0].y;
#pragma unroll
    for (int u = 1; u < 4; u++) {
        float nAr = a[u].x*Atr - a[u].y*Ati;
        float nAi = a[u].x*Ati + a[u].y*Atr;
        float nBr = a[u].x*Btr - a[u].y*Bti + b[u].x;
        float nBi = a[u].x*Bti + a[u].y*Btr + b[u].y;
        Atr = nAr; Ati = nAi; Btr = nBr; Bti = nBi;
    }

    /* Kogge-Stone inclusive scan over lanes: cur = cur ∘ prev         */
#pragma unroll
    for (int off = 1; off < 32; off <<= 1) {
        float pAr = __shfl_up_sync(FULL, Atr, off);
        float pAi = __shfl_up_sync(FULL, Ati, off);
        float pBr = __shfl_up_sync(FULL, Btr, off);
        float pBi = __shfl_up_sync(FULL, Bti, off);
        if (lane >= off) {
            float nAr = Atr*pAr - Ati*pAi;
            float nAi = Atr*pAi + Ati*pAr;
            float nBr = Atr*pBr - Ati*pBi + Btr;
            float nBi = Atr*pBi + Ati*pBr + Bti;
            Atr = nAr; Ati = nAi; Btr = nBr; Bti = nBi;
        }
    }

    /* exclusive = shifted inclusive; identity at lane 0               */
    float eAr = __shfl_up_sync(FULL, Atr, 1);
    float eAi = __shfl_up_sync(FULL, Ati, 1);
    float eBr = __shfl_up_sync(FULL, Btr, 1);
    float eBi = __shfl_up_sync(FULL, Bti, 1);
    if (lane == 0) { eAr = 1.f; eAi = 0.f; eBr = 0.f; eBi = 0.f; }

    /* carry state entering this lane's first chunk                    */
    const float s0r = st_re[ch], s0i = st_im[ch];
    float sr = eAr*s0r - eAi*s0i + eBr;
    float si = eAr*s0i + eAi*s0r + eBi;

    /* replay local chunks: write carry, advance                       */
#pragma unroll
    for (int u = 0; u < 4; u++) {
        int j = lane*4 + u;
        g_carry[j*CH + ch] = make_float2(sr, si);
        float nr = a[u].x*sr - a[u].y*si + b[u].x;
        float ni = a[u].x*si + a[u].y*sr + b[u].y;
        sr = nr; si = ni;
    }

    if (lane == 31) {                    /* final state of channel     */
        if (fs_mode == 1) {
            out_fs[ch] = sr;
        } else {
            out_fs[2*ch]   = sr;
            out_fs[2*ch+1] = si;
        }
    }
}

/* Phase C: replay chunks; write z_in fp16 [T, 2048]                   */
__global__ __launch_bounds__(1024)
void expand_kernel(const float* __restrict__ ffa_a, const float* __restrict__ ffa_b)
{
    __shared__ float sx[CHUNK*TRACE_D];
    __shared__ unsigned char ss[CHUNK];
    const int chunk = blockIdx.x, tid = threadIdx.x;
    const float* src = g_gx + chunk*CHUNK*TRACE_D;
    for (int i = tid; i < CHUNK*TRACE_D; i += 1024) sx[i] = src[i];
    if (tid < CHUNK) ss[tid] = g_start[chunk*CHUNK + tid];
    __syncthreads();

    const int m = tid >> 4, c = tid & 15;
    const float r  = expf(-fabsf(ffa_a[m]));
    const float gr = r * cosf(ffa_b[c]);
    const float gi = r * sinf(ffa_b[c]);

    float2 s = g_carry[chunk*CH + tid];
    const size_t zo = (size_t)chunk*CHUNK*2*CH + m*32 + c;
#pragma unroll 2
    for (int t = 0; t < CHUNK; t++) {
        float xv = sx[t*TRACE_D + m];
        float nr, ni;
        if (ss[t]) { nr = xv; ni = 0.f; }
        else { nr = gr*s.x - gi*s.y + xv; ni = gr*s.y + gi*s.x; }
        s.x = nr; s.y = ni;
        size_t o = zo + (size_t)t*2048;
        g_zf[o]      = __float2half(nr);
        g_zf[o + 16] = __float2half(ni);
    }
}

/* ------------------------------------------------------------------ */
/* epilogue: zg = z*sig(go); LN(zg) + skip*(1-sig(go))                 */
/* ------------------------------------------------------------------ */
__global__ __launch_bounds__(256)
void ln_kernel(float* __restrict__ out)
{
    const int row = blockIdx.x, tid = threadIdx.x;
    const float* zp = g_zr + (size_t)row*OUT_D;
    const float* gp = g_gs + (size_t)row*2*OUT_D;
    const float* sp = gp + OUT_D;

    float zg[4], sk[4], s1 = 0.f, s2 = 0.f;
#pragma unroll
    for (int i = 0; i < 4; i++) {
        int c = tid + i*256;
        float g  = 1.f / (1.f + expf(-gp[c]));
        float zv = zp[c] * g;
        zg[i] = zv; s1 += zv; s2 += zv*zv;
        sk[i] = sp[c] * (1.f - g);
    }
#pragma unroll
    for (int o = 16; o > 0; o >>= 1) {
        s1 += __shfl_xor_sync(0xffffffffu, s1, o);
        s2 += __shfl_xor_sync(0xffffffffu, s2, o);
    }
    __shared__ float sh1[8], sh2[8];
    const int warp = tid >> 5, lane = tid & 31;
    if (lane == 0) { sh1[warp] = s1; sh2[warp] = s2; }
    __syncthreads();
    if (tid == 0) {
        float t1 = 0.f, t2 = 0.f;
        for (int w = 0; w < 8; w++) { t1 += sh1[w]; t2 += sh2[w]; }
        sh1[0] = t1; sh2[0] = t2;
    }
    __syncthreads();
    const float mu   = sh1[0] * (1.f/OUT_D);
    const float var  = sh2[0] * (1.f/OUT_D) - mu*mu;
    const float rstd = rsqrtf(var + 1e-5f);
    float* op = out + (size_t)row*OUT_D;
#pragma unroll
    for (int i = 0; i < 4; i++) {
        int c = tid + i*256;
        op[c] = (zg[i] - mu) * rstd + sk[i];
    }
}

/* ------------------------------------------------------------------ */
extern "C" void kernel_launch(void* const* d_in, const int* in_sizes, int n_in,
                              void* d_out, int out_size)
{
    (void)in_sizes; (void)n_in;
    const float* x      = (const float*)d_in[0];
    const float* st_re  = (const float*)d_in[1];
    const float* st_im  = (const float*)d_in[2];
    const unsigned char* start = (const unsigned char*)d_in[3];
    const float* pre_w  = (const float*)d_in[5];
    const float* pre_b  = (const float*)d_in[6];
    const float* gi_w   = (const float*)d_in[7];
    const float* gi_b   = (const float*)d_in[8];
    const float* go_w   = (const float*)d_in[9];
    const float* go_b   = (const float*)d_in[10];
    const float* skip_w = (const float*)d_in[11];
    const float* skip_b = (const float*)d_in[12];
    const float* mix_w  = (const float*)d_in[13];
    const float* mix_b  = (const float*)d_in[14];
    const float* ffa_a  = (const float*)d_in[15];
    const float* ffa_b  = (const float*)d_in[16];
    float* out = (float*)d_out;

    float *pzr, *pgs, *pfsd, *pbgs;
    __half *pxh, *pxl, *pzf, *pgsf, *pmxf, *pwch, *pwcl;
    cudaGetSymbolAddress((void**)&pzr,   g_zr);
    cudaGetSymbolAddress((void**)&pgs,   g_gs);
    cudaGetSymbolAddress((void**)&pfsd,  g_fsdump);
    cudaGetSymbolAddress((void**)&pbgs,  g_bgs);
    cudaGetSymbolAddress((void**)&pxh,   g_xh);
    cudaGetSymbolAddress((void**)&pxl,   g_xl);
    cudaGetSymbolAddress((void**)&pzf,   g_zf);
    cudaGetSymbolAddress((void**)&pgsf,  g_gsf);
    cudaGetSymbolAddress((void**)&pmxf,  g_mxf);
    cudaGetSymbolAddress((void**)&pwch,  g_wch);
    cudaGetSymbolAddress((void**)&pwcl,  g_wcl);

    /* final_state placement (proven in round 3): real-part-only pack  */
    const long base = (long)T_STEPS * OUT_D;                  /* 8388608 */
    const long osz  = (long)out_size;
    float* fs_dst  = pfsd;
    int    fs_mode = 0;
    if (osz == base + CH) {            /* 8389632: real-part-only pack */
        fs_dst  = out + base;
        fs_mode = 1;
    } else if (osz >= base + 2*CH) {
        fs_dst  = out + base;
        fs_mode = 0;
    } else if (2*osz >= base + 2*CH) {
        fs_dst  = out + base;
        fs_mode = 0;
    }

    static int inited = 0;
    if (!inited) {
        cudaFuncSetAttribute(hgemm_dual,        cudaFuncAttributeMaxDynamicSharedMemorySize, DUAL_SMEM);
        cudaFuncSetAttribute(hgemm_small_gated, cudaFuncAttributeMaxDynamicSharedMemorySize, SMALL_SMEM);
        inited = 1;
    }

    prep_start<<<1, 1024>>>(start);
    split_all<<<(CTq + 255)/256, 256>>>(x, gi_w, pre_w, go_w, skip_w, mix_w, go_b, skip_b);

    /* small GEMM + gated + scan-A fused (block j == chunk j)          */
    hgemm_small_gated<<<T_STEPS/64, 256, SMALL_SMEM>>>(pxh, pxl, pwch, pwcl,
                                                       gi_b, pre_b, ffa_a, ffa_b);
    carry_scan<<<32, 1024>>>(st_re, st_im, fs_dst, fs_mode);
    expand_kernel<<<NCHUNK, 1024>>>(ffa_a, ffa_b);

    hgemm_dual<<<1536, 256, DUAL_SMEM>>>(pxh, pgsf, pbgs, pgs,
                                         pzf, pmxf, mix_b, pzr);

    ln_kernel<<<T_STEPS, 256>>>(out);
}

// round 12
// speedup vs baseline: 1.1504x; 1.0519x over previous
#include <cuda_runtime.h>
#include <cuda_fp16.h>
#include <stdint.h>

#define T_STEPS 8192
#define INPUT_D 1024
#define TRACE_D 64
#define CTX_D   16
#define OUT_D   1024
#define CH      (TRACE_D*CTX_D)      /* 1024 channels */
#define CHUNK   64
#define NCHUNK  (T_STEPS/CHUNK)      /* 128 */

/* ------------------------------------------------------------------ */
/* scratch (device globals: allocation-free rule)                      */
/* ------------------------------------------------------------------ */
__device__ float  g_gx[T_STEPS*TRACE_D];      /* gated_x                */
__device__ float2 g_Ac[NCHUNK*CH];
__device__ float2 g_Bc[NCHUNK*CH];
__device__ float2 g_carry[NCHUNK*CH];
__device__ float  g_zr [(size_t)T_STEPS*OUT_D];
__device__ float  g_gs [(size_t)T_STEPS*2*OUT_D];   /* go|skip fused, N=2048 */
__device__ unsigned char g_start[T_STEPS];
__device__ float  g_fsdump[2*CH];
__device__ float  g_bgs[2*OUT_D];             /* go_b | skip_b          */

/* fp16 operands for tensor-core GEMMs */
__device__ __half g_xh[(size_t)T_STEPS*INPUT_D];
__device__ __half g_xl[(size_t)T_STEPS*INPUT_D];
__device__ __half g_zf[(size_t)T_STEPS*2*CH];
__device__ __half g_gsf[2*OUT_D*INPUT_D];
__device__ __half g_mxf[OUT_D*2*CH];
__device__ __half g_wch[128*INPUT_D], g_wcl[128*INPUT_D];

/* ------------------------------------------------------------------ */
/* PTX helpers                                                         */
/* ------------------------------------------------------------------ */
__device__ __forceinline__ uint32_t smem_u32(const void* p){
    uint32_t a;
    asm("{ .reg .u64 t; cvta.to.shared.u64 t, %1; cvt.u32.u64 %0, t; }"
        : "=r"(a) : "l"(p));
    return a;
}
__device__ __forceinline__ void cpa16(uint32_t s, const void* g){
    asm volatile("cp.async.cg.shared.global [%0], [%1], 16;"
                 :: "r"(s), "l"(g) : "memory");
}
__device__ __forceinline__ void cpa_commit(){
    asm volatile("cp.async.commit_group;" ::: "memory");
}
template<int N>
__device__ __forceinline__ void cpa_wait(){
    asm volatile("cp.async.wait_group %0;" :: "n"(N) : "memory");
}
__device__ __forceinline__ void ldsm4(uint32_t* r, uint32_t a){
    asm volatile("ldmatrix.sync.aligned.m8n8.x4.shared.b16 {%0,%1,%2,%3}, [%4];"
                 : "=r"(r[0]), "=r"(r[1]), "=r"(r[2]), "=r"(r[3]) : "r"(a));
}
__device__ __forceinline__ void mma_f16(float* d, const uint32_t* a, const uint32_t* b){
    asm volatile(
        "mma.sync.aligned.m16n8k16.row.col.f32.f16.f16.f32 "
        "{%0,%1,%2,%3}, {%4,%5,%6,%7}, {%8,%9}, {%0,%1,%2,%3};"
        : "+f"(d[0]), "+f"(d[1]), "+f"(d[2]), "+f"(d[3])
        : "r"(a[0]), "r"(a[1]), "r"(a[2]), "r"(a[3]), "r"(b[0]), "r"(b[1]));
}
__device__ __forceinline__ uint32_t sw128(uint32_t b){
    return b ^ ((b >> 3) & 0x70);
}

#define DUAL_SMEM  (3*32768)                   /* 98304: 2 CTAs/SM      */
#define SMALL_SMEM (3*(2*8192 + 2*16384))      /* 147456                */

/* ------------------------------------------------------------------ */
/* DUAL big GEMM, fp16 single-pass, fp32 acc (proven config).          */
/* job0 (bid<1024):  g_gs = xh @ gsf^T + bgs   (N=2048, K=1024)        */
/* job1 (bid>=1024): g_zr = zf @ mxf^T + mix_b (N=1024, K=2048)        */
/* ------------------------------------------------------------------ */
__global__ __launch_bounds__(256, 2)
void hgemm_dual(const __half* __restrict__ A0, const __half* __restrict__ W0,
                const float* __restrict__ b0, float* __restrict__ C0,
                const __half* __restrict__ A1, const __half* __restrict__ W1,
                const float* __restrict__ b1, float* __restrict__ C1)
{
    const int TSZ = 16384, STAGE = 32768;
    extern __shared__ char smem[];
    const uint32_t sb = smem_u32(smem);
    const int tid = threadIdx.x;
    const int wid = tid >> 5, l = tid & 31;

    const int bid  = blockIdx.x;
    const bool j1  = (bid >= 1024);
    const int lb   = j1 ? bid - 1024 : bid;
    const int bm   = (lb & 63) * 128;
    const int bn   = (lb >> 6) * 128;
    const int N    = j1 ? OUT_D : 2*OUT_D;
    const int K    = j1 ? 2*CH  : INPUT_D;
    const __half* A = j1 ? A1 : A0;
    const __half* W = j1 ? W1 : W0;
    const float* bias = j1 ? b1 : b0;
    float* C = j1 ? C1 : C0;

    const int wm0 = (wid & 3) * 32, wn0 = (wid >> 2) * 64;

    float acc[2][8][4];
#pragma unroll
    for (int mt = 0; mt < 2; mt++)
#pragma unroll
        for (int nt = 0; nt < 8; nt++)
#pragma unroll
            for (int j = 0; j < 4; j++) acc[mt][nt][j] = 0.f;

    const int nk = K >> 6;

    auto issue = [&](int s, int k0){
        const uint32_t st = sb + s * STAGE;
#pragma unroll
        for (int it = 0; it < 4; it++) {
            int idx = tid + it*256;
            int row = idx >> 3, cv = idx & 7;
            uint32_t sw = sw128((uint32_t)(row*128 + cv*16));
            cpa16(st +       sw, A + (size_t)(bm + row) * K + k0 + cv*8);
            cpa16(st + TSZ + sw, W + (size_t)(bn + row) * K + k0 + cv*8);
        }
        cpa_commit();
    };

    issue(0, 0);
    issue(1, 64);
    for (int kt = 0; kt < nk; kt++) {
        if (kt + 1 < nk) cpa_wait<1>(); else cpa_wait<0>();
        __syncthreads();
        if (kt + 2 < nk) issue((kt+2) % 3, (kt+2) << 6);

        const uint32_t st  = sb + (kt % 3) * STAGE;
        const uint32_t A_s = st, B_s = st + TSZ;

#pragma unroll
        for (int kk = 0; kk < 4; kk++) {
            uint32_t af[2][4];
#pragma unroll
            for (int mt = 0; mt < 2; mt++) {
                int row = wm0 + mt*16 + (l & 15);
                uint32_t sw = sw128((uint32_t)(row*128 + kk*32 + (l >> 4)*16));
                ldsm4(af[mt], A_s + sw);
            }
            uint32_t bf[4][4];
#pragma unroll
            for (int p = 0; p < 4; p++) {
                int row = wn0 + p*16 + ((l >> 4) & 1)*8 + (l & 7);
                uint32_t sw = sw128((uint32_t)(row*128 + kk*32 + ((l >> 3) & 1)*16));
                ldsm4(bf[p], B_s + sw);
            }
#pragma unroll
            for (int mt = 0; mt < 2; mt++)
#pragma unroll
                for (int nt = 0; nt < 8; nt++)
                    mma_f16(acc[mt][nt], af[mt], &bf[nt >> 1][(nt & 1)*2]);
        }
    }

#pragma unroll
    for (int mt = 0; mt < 2; mt++) {
        int row0 = bm + wm0 + mt*16 + (l >> 2);
#pragma unroll
        for (int nt = 0; nt < 8; nt++) {
            int col = bn + wn0 + nt*8 + (l & 3)*2;
            float bb0 = bias[col], bb1 = bias[col+1];
            float* c0 = C + (size_t)row0 * N + col;
            c0[0] = acc[mt][nt][0] + bb0;
            c0[1] = acc[mt][nt][1] + bb1;
            float* c1 = C + (size_t)(row0 + 8) * N + col;
            c1[0] = acc[mt][nt][2] + bb0;
            c1[1] = acc[mt][nt][3] + bb1;
        }
    }
}

/* ------------------------------------------------------------------ */
/* small GEMM (BM=64, N=128, K=1024), fp16 hi/lo 3-pass, with FUSED    */
/* gated epilogue AND fused scan phase-A (block j == chunk j).         */
/* ------------------------------------------------------------------ */
__global__ __launch_bounds__(256, 1)
void hgemm_small_gated(const __half* __restrict__ Ah, const __half* __restrict__ Al,
                       const __half* __restrict__ Wh, const __half* __restrict__ Wl,
                       const float* __restrict__ gi_b, const float* __restrict__ pre_b,
                       const float* __restrict__ ffa_a, const float* __restrict__ ffa_b)
{
    const int ASZ = 8192, STAGE = 2*ASZ + 2*16384, K = INPUT_D;
    extern __shared__ char smem[];
    const uint32_t sb = smem_u32(smem);
    const int tid = threadIdx.x;
    const int wid = tid >> 5, l = tid & 31;
    const int bm = blockIdx.x * 64;
    const int wm0 = (wid & 3) * 16, wn0 = (wid >> 2) * 64;
    const int lr = tid >> 3, lc = tid & 7;

    float acc[8][4];
#pragma unroll
    for (int nt = 0; nt < 8; nt++)
#pragma unroll
        for (int j = 0; j < 4; j++) acc[nt][j] = 0.f;

    const int nk = K >> 6;       /* 16 */

    auto issue = [&](int s, int k0){
        const uint32_t st = sb + s * STAGE;
#pragma unroll
        for (int it = 0; it < 2; it++) {
            int idx = tid + it*256;
            int row = idx >> 3, cv = idx & 7;
            uint32_t sw = sw128((uint32_t)(row*128 + cv*16));
            size_t ao = (size_t)(bm + row) * K + k0 + cv*8;
            cpa16(st +       sw, Ah + ao);
            cpa16(st + ASZ + sw, Al + ao);
        }
#pragma unroll
        for (int it = 0; it < 4; it++) {
            int row = lr + it*32, cv = lc;
            uint32_t sw = sw128((uint32_t)(row*128 + cv*16));
            size_t bo = (size_t)row * K + k0 + cv*8;
            cpa16(st + 2*ASZ +         sw, Wh + bo);
            cpa16(st + 2*ASZ + 16384 + sw, Wl + bo);
        }
        cpa_commit();
    };

    issue(0, 0);
    issue(1, 64);
    for (int kt = 0; kt < nk; kt++) {
        if (kt + 1 < nk) cpa_wait<1>(); else cpa_wait<0>();
        __syncthreads();
        if (kt + 2 < nk) issue((kt+2) % 3, (kt+2) << 6);

        const uint32_t st  = sb + (kt % 3) * STAGE;
        const uint32_t A_h = st, A_l = st + ASZ, B_h = st + 2*ASZ, B_l = st + 2*ASZ + 16384;

#pragma unroll
        for (int kk = 0; kk < 4; kk++) {
            uint32_t ah[4], al[4];
            {
                int row = wm0 + (l & 15);
                uint32_t sw = sw128((uint32_t)(row*128 + kk*32 + (l >> 4)*16));
                ldsm4(ah, A_h + sw);
                ldsm4(al, A_l + sw);
            }
            uint32_t bh[4][4], bl[4][4];
#pragma unroll
            for (int p = 0; p < 4; p++) {
                int row = wn0 + p*16 + ((l >> 4) & 1)*8 + (l & 7);
                uint32_t sw = sw128((uint32_t)(row*128 + kk*32 + ((l >> 3) & 1)*16));
                ldsm4(bh[p], B_h + sw);
                ldsm4(bl[p], B_l + sw);
            }
#pragma unroll
            for (int nt = 0; nt < 8; nt++) {
                const uint32_t* bhp = &bh[nt >> 1][(nt & 1)*2];
                const uint32_t* blp = &bl[nt >> 1][(nt & 1)*2];
                mma_f16(acc[nt], ah, bhp);
                mma_f16(acc[nt], ah, blp);
                mma_f16(acc[nt], al, bhp);
            }
        }
    }

    /* ---- fused epilogue 1: stage Y into smem --------------------- */
    __syncthreads();
    float* sY  = (float*)smem;                 /* [64][130]           */
    float* gxs = sY + 64*130;                  /* [64][65] gated_x    */
    unsigned char* ssm = (unsigned char*)(gxs + 64*65);
    const int YS = 130;
    {
        int row0 = wm0 + (l >> 2);
#pragma unroll
        for (int nt = 0; nt < 8; nt++) {
            int col = wn0 + nt*8 + (l & 3)*2;
            sY[row0*YS + col]     = acc[nt][0];
            sY[row0*YS + col + 1] = acc[nt][1];
            sY[(row0+8)*YS + col]     = acc[nt][2];
            sY[(row0+8)*YS + col + 1] = acc[nt][3];
        }
    }
    if (tid < 64) ssm[tid] = g_start[bm + tid];
    __syncthreads();

    /* ---- fused epilogue 2: gated_x -> gmem + smem ---------------- */
    const int m = tid & 63;
    const float gb = gi_b[m], pb = pre_b[m];
#pragma unroll
    for (int i = 0; i < 16; i++) {
        int r = (tid >> 6) + i*4;
        float y1 = sY[r*YS + m]      + gb;
        float y2 = sY[r*YS + 64 + m] + pb;
        float gx = y2 / (1.f + expf(-y1));
        g_gx[(size_t)(bm + r)*TRACE_D + m] = gx;
        gxs[r*65 + m] = gx;
    }
    __syncthreads();

    /* ---- fused epilogue 3: scan phase-A (4 channels/thread) ------ */
    float gr[4], gi_[4], Ar[4], Ai[4], Br[4], Bi[4];
    int mm[4];
#pragma unroll
    for (int q = 0; q < 4; q++) {
        int ch = tid + q*256;
        mm[q] = ch >> 4;
        int cc = ch & 15;
        float rr = expf(-fabsf(ffa_a[mm[q]]));
        gr[q] = rr * cosf(ffa_b[cc]);
        gi_[q] = rr * sinf(ffa_b[cc]);
        Ar[q] = 1.f; Ai[q] = 0.f; Br[q] = 0.f; Bi[q] = 0.f;
    }
#pragma unroll 2
    for (int t = 0; t < CHUNK; t++) {
        bool st = ssm[t];
#pragma unroll
        for (int q = 0; q < 4; q++) {
            float xv = gxs[t*65 + mm[q]];
            if (st) { Ar[q] = 0.f; Ai[q] = 0.f; Br[q] = xv; Bi[q] = 0.f; }
            else {
                float nAr = gr[q]*Ar[q] - gi_[q]*Ai[q];
                float nAi = gr[q]*Ai[q] + gi_[q]*Ar[q];
                float nBr = gr[q]*Br[q] - gi_[q]*Bi[q] + xv;
                float nBi = gr[q]*Bi[q] + gi_[q]*Br[q];
                Ar[q] = nAr; Ai[q] = nAi; Br[q] = nBr; Bi[q] = nBi;
            }
        }
    }
#pragma unroll
    for (int q = 0; q < 4; q++) {
        int ch = tid + q*256;
        g_Ac[blockIdx.x*CH + ch] = make_float2(Ar[q], Ai[q]);
        g_Bc[blockIdx.x*CH + ch] = make_float2(Br[q], Bi[q]);
    }
}

/* ------------------------------------------------------------------ */
/* merged conversion kernel (+ trailing block does start-flag prep)    */
/* ------------------------------------------------------------------ */
#define XQ  2097152
#define WQ  16384
#define GQ  262144
#define MQ  524288
#define C1q (XQ)
#define C2q (C1q + WQ)
#define C3q (C2q + WQ)
#define C4q (C3q + GQ)
#define C5q (C4q + GQ)
#define C6q (C5q + MQ)
#define CTq (C6q + 512)
#define SPLIT_BLOCKS ((CTq + 255)/256)

__device__ __forceinline__ void split_hl(const float4* __restrict__ s, long i,
                                         uint2* __restrict__ h, uint2* __restrict__ l)
{
    float4 v = s[i];
    __half h0 = __float2half(v.x), h1 = __float2half(v.y);
    __half h2 = __float2half(v.z), h3 = __float2half(v.w);
    __half l0 = __float2half(v.x - __half2float(h0));
    __half l1 = __float2half(v.y - __half2float(h1));
    __half l2 = __float2half(v.z - __half2float(h2));
    __half l3 = __float2half(v.w - __half2float(h3));
    uint2 uh, ul;
    uh.x = (uint32_t)__half_as_ushort(h0) | ((uint32_t)__half_as_ushort(h1) << 16);
    uh.y = (uint32_t)__half_as_ushort(h2) | ((uint32_t)__half_as_ushort(h3) << 16);
    ul.x = (uint32_t)__half_as_ushort(l0) | ((uint32_t)__half_as_ushort(l1) << 16);
    ul.y = (uint32_t)__half_as_ushort(l2) | ((uint32_t)__half_as_ushort(l3) << 16);
    h[i] = uh; l[i] = ul;
}
__device__ __forceinline__ void cvt_h(const float4* __restrict__ s, long i,
                                      uint2* __restrict__ o)
{
    float4 v = s[i];
    uint2 u;
    u.x = (uint32_t)__half_as_ushort(__float2half(v.x))
        | ((uint32_t)__half_as_ushort(__float2half(v.y)) << 16);
    u.y = (uint32_t)__half_as_ushort(__float2half(v.z))
        | ((uint32_t)__half_as_ushort(__float2half(v.w)) << 16);
    o[i] = u;
}

__global__ void split_all(const float* __restrict__ x,
                          const float* __restrict__ gi_w, const float* __restrict__ pre_w,
                          const float* __restrict__ go_w, const float* __restrict__ skip_w,
                          const float* __restrict__ mix_w,
                          const float* __restrict__ go_b, const float* __restrict__ skip_b,
                          const unsigned char* __restrict__ s8)
{
    /* trailing block: start-flag classify + canonicalize             */
    if (blockIdx.x == SPLIT_BLOCKS) {
        __shared__ int flags[3];
        const int tid = threadIdx.x;
        if (tid < 3) flags[tid] = 0;
        __syncthreads();
        const unsigned int* s32 = (const unsigned int*)s8;
        for (int i = tid; i < 2048; i += 256) {
            unsigned v = s32[i];
            if (v == 0u) continue;
            else if (v == 1u)           atomicOr(&flags[0], 1);
            else if (v == 0x3f800000u)  atomicOr(&flags[1], 1);
            else                        atomicOr(&flags[2], 1);
        }
        __syncthreads();
        const int mode = flags[2] ? 0 : (flags[1] ? 2 : (flags[0] ? 1 : 0));
#pragma unroll
        for (int i = 0; i < 32; i++) {
            int idx = tid + i*256;
            unsigned char v;
            if (mode == 1)      v = (((const int*)  s8)[idx] != 0);
            else if (mode == 2) v = (((const float*)s8)[idx] != 0.f);
            else                v = (s8[idx] != 0);
            g_start[idx] = v;
        }
        return;
    }

    long i = (long)blockIdx.x * blockDim.x + threadIdx.x;
    if (i >= CTq) return;
    if (i < C1q)      split_hl((const float4*)x,     i,       (uint2*)g_xh,  (uint2*)g_xl);
    else if (i < C2q) split_hl((const float4*)gi_w,  i - C1q, (uint2*)g_wch, (uint2*)g_wcl);
    else if (i < C3q) split_hl((const float4*)pre_w, i - C2q,
                               (uint2*)(g_wch + 64*INPUT_D), (uint2*)(g_wcl + 64*INPUT_D));
    else if (i < C4q) cvt_h((const float4*)go_w,   i - C3q, (uint2*)g_gsf);
    else if (i < C5q) cvt_h((const float4*)skip_w, i - C4q,
                            (uint2*)(g_gsf + (size_t)OUT_D*INPUT_D));
    else if (i < C6q) cvt_h((const float4*)mix_w,  i - C5q, (uint2*)g_mxf);
    else {
        long i2 = i - C6q;
        float4 v = (i2 < 256) ? ((const float4*)go_b)[i2] : ((const float4*)skip_b)[i2 - 256];
        ((float4*)g_bgs)[i2] = v;
    }
}

/* ------------------------------------------------------------------ */
/* Phase B: PARALLEL warp-scan carry. 1 warp per channel.              */
/* grid=128, block=256 -> 1024 warps spread over 128 SMs.              */
/* ------------------------------------------------------------------ */
__global__ __launch_bounds__(256)
void carry_scan(const float* __restrict__ st_re, const float* __restrict__ st_im,
                float* __restrict__ out_fs, int fs_mode)
{
    const int tid  = threadIdx.x;
    const int wid  = tid >> 5, lane = tid & 31;
    const int ch   = blockIdx.x * 8 + wid;           /* 0..1023 */
    const unsigned FULL = 0xffffffffu;

    /* load 4 chunk affines, compose serially: f = f3∘f2∘f1∘f0        */
    float2 a[4], b[4];
#pragma unroll
    for (int u = 0; u < 4; u++) {
        int j = lane*4 + u;
        a[u] = g_Ac[j*CH + ch];
        b[u] = g_Bc[j*CH + ch];
    }
    float Atr = a[0].x, Ati = a[0].y, Btr = b[0].x, Bti = b[0].y;
#pragma unroll
    for (int u = 1; u < 4; u++) {
        float nAr = a[u].x*Atr - a[u].y*Ati;
        float nAi = a[u].x*Ati + a[u].y*Atr;
        float nBr = a[u].x*Btr - a[u].y*Bti + b[u].x;
        float nBi = a[u].x*Bti + a[u].y*Btr + b[u].y;
        Atr = nAr; Ati = nAi; Btr = nBr; Bti = nBi;
    }

    /* Kogge-Stone inclusive scan over lanes: cur = cur ∘ prev         */
#pragma unroll
    for (int off = 1; off < 32; off <<= 1) {
        float pAr = __shfl_up_sync(FULL, Atr, off);
        float pAi = __shfl_up_sync(FULL, Ati, off);
        float pBr = __shfl_up_sync(FULL, Btr, off);
        float pBi = __shfl_up_sync(FULL, Bti, off);
        if (lane >= off) {
            float nAr = Atr*pAr - Ati*pAi;
            float nAi = Atr*pAi + Ati*pAr;
            float nBr = Atr*pBr - Ati*pBi + Btr;
            float nBi = Atr*pBi + Ati*pBr + Bti;
            Atr = nAr; Ati = nAi; Btr = nBr; Bti = nBi;
        }
    }

    /* exclusive = shifted inclusive; identity at lane 0               */
    float eAr = __shfl_up_sync(FULL, Atr, 1);
    float eAi = __shfl_up_sync(FULL, Ati, 1);
    float eBr = __shfl_up_sync(FULL, Btr, 1);
    float eBi = __shfl_up_sync(FULL, Bti, 1);
    if (lane == 0) { eAr = 1.f; eAi = 0.f; eBr = 0.f; eBi = 0.f; }

    /* carry state entering this lane's first chunk                    */
    const float s0r = st_re[ch], s0i = st_im[ch];
    float sr = eAr*s0r - eAi*s0i + eBr;
    float si = eAr*s0i + eAi*s0r + eBi;

    /* replay local chunks: write carry, advance                       */
#pragma unroll
    for (int u = 0; u < 4; u++) {
        int j = lane*4 + u;
        g_carry[j*CH + ch] = make_float2(sr, si);
        float nr = a[u].x*sr - a[u].y*si + b[u].x;
        float ni = a[u].x*si + a[u].y*sr + b[u].y;
        sr = nr; si = ni;
    }

    if (lane == 31) {                    /* final state of channel     */
        if (fs_mode == 1) {
            out_fs[ch] = sr;
        } else {
            out_fs[2*ch]   = sr;
            out_fs[2*ch+1] = si;
        }
    }
}

/* Phase C: replay chunks; write z_in fp16 [T, 2048]                   */
__global__ __launch_bounds__(1024)
void expand_kernel(const float* __restrict__ ffa_a, const float* __restrict__ ffa_b)
{
    __shared__ float sx[CHUNK*TRACE_D];
    __shared__ unsigned char ss[CHUNK];
    const int chunk = blockIdx.x, tid = threadIdx.x;
    const float* src = g_gx + chunk*CHUNK*TRACE_D;
    for (int i = tid; i < CHUNK*TRACE_D; i += 1024) sx[i] = src[i];
    if (tid < CHUNK) ss[tid] = g_start[chunk*CHUNK + tid];
    __syncthreads();

    const int m = tid >> 4, c = tid & 15;
    const float r  = expf(-fabsf(ffa_a[m]));
    const float gr = r * cosf(ffa_b[c]);
    const float gi = r * sinf(ffa_b[c]);

    float2 s = g_carry[chunk*CH + tid];
    const size_t zo = (size_t)chunk*CHUNK*2*CH + m*32 + c;
#pragma unroll 2
    for (int t = 0; t < CHUNK; t++) {
        float xv = sx[t*TRACE_D + m];
        float nr, ni;
        if (ss[t]) { nr = xv; ni = 0.f; }
        else { nr = gr*s.x - gi*s.y + xv; ni = gr*s.y + gi*s.x; }
        s.x = nr; s.y = ni;
        size_t o = zo + (size_t)t*2048;
        g_zf[o]      = __float2half(nr);
        g_zf[o + 16] = __float2half(ni);
    }
}

/* ------------------------------------------------------------------ */
/* epilogue: zg = z*sig(go); LN(zg) + skip*(1-sig(go)); float4 I/O     */
/* ------------------------------------------------------------------ */
__global__ __launch_bounds__(256)
void ln_kernel(float* __restrict__ out)
{
    const int row = blockIdx.x, tid = threadIdx.x;
    const float4* zp = (const float4*)(g_zr + (size_t)row*OUT_D);
    const float4* gp = (const float4*)(g_gs + (size_t)row*2*OUT_D);
    const float4* sp = (const float4*)(g_gs + (size_t)row*2*OUT_D + OUT_D);

    float4 zv4 = zp[tid], gv4 = gp[tid], sv4 = sp[tid];
    float zg[4], sk[4], s1 = 0.f, s2 = 0.f;
    {
        const float* zv = &zv4.x; const float* gv = &gv4.x; const float* sv = &sv4.x;
#pragma unroll
        for (int i = 0; i < 4; i++) {
            float g  = 1.f / (1.f + expf(-gv[i]));
            float z  = zv[i] * g;
            zg[i] = z; s1 += z; s2 += z*z;
            sk[i] = sv[i] * (1.f - g);
        }
    }
#pragma unroll
    for (int o = 16; o > 0; o >>= 1) {
        s1 += __shfl_xor_sync(0xffffffffu, s1, o);
        s2 += __shfl_xor_sync(0xffffffffu, s2, o);
    }
    __shared__ float sh1[8], sh2[8];
    const int warp = tid >> 5, lane = tid & 31;
    if (lane == 0) { sh1[warp] = s1; sh2[warp] = s2; }
    __syncthreads();
    if (tid == 0) {
        float t1 = 0.f, t2 = 0.f;
        for (int w = 0; w < 8; w++) { t1 += sh1[w]; t2 += sh2[w]; }
        sh1[0] = t1; sh2[0] = t2;
    }
    __syncthreads();
    const float mu   = sh1[0] * (1.f/OUT_D);
    const float var  = sh2[0] * (1.f/OUT_D) - mu*mu;
    const float rstd = rsqrtf(var + 1e-5f);
    float4 o4;
    o4.x = (zg[0] - mu) * rstd + sk[0];
    o4.y = (zg[1] - mu) * rstd + sk[1];
    o4.z = (zg[2] - mu) * rstd + sk[2];
    o4.w = (zg[3] - mu) * rstd + sk[3];
    ((float4*)(out + (size_t)row*OUT_D))[tid] = o4;
}

/* ------------------------------------------------------------------ */
extern "C" void kernel_launch(void* const* d_in, const int* in_sizes, int n_in,
                              void* d_out, int out_size)
{
    (void)in_sizes; (void)n_in;
    const float* x      = (const float*)d_in[0];
    const float* st_re  = (const float*)d_in[1];
    const float* st_im  = (const float*)d_in[2];
    const unsigned char* start = (const unsigned char*)d_in[3];
    const float* pre_w  = (const float*)d_in[5];
    const float* pre_b  = (const float*)d_in[6];
    const float* gi_w   = (const float*)d_in[7];
    const float* gi_b   = (const float*)d_in[8];
    const float* go_w   = (const float*)d_in[9];
    const float* go_b   = (const float*)d_in[10];
    const float* skip_w = (const float*)d_in[11];
    const float* skip_b = (const float*)d_in[12];
    const float* mix_w  = (const float*)d_in[13];
    const float* mix_b  = (const float*)d_in[14];
    const float* ffa_a  = (const float*)d_in[15];
    const float* ffa_b  = (const float*)d_in[16];
    float* out = (float*)d_out;

    float *pzr, *pgs, *pfsd, *pbgs;
    __half *pxh, *pxl, *pzf, *pgsf, *pmxf, *pwch, *pwcl;
    cudaGetSymbolAddress((void**)&pzr,   g_zr);
    cudaGetSymbolAddress((void**)&pgs,   g_gs);
    cudaGetSymbolAddress((void**)&pfsd,  g_fsdump);
    cudaGetSymbolAddress((void**)&pbgs,  g_bgs);
    cudaGetSymbolAddress((void**)&pxh,   g_xh);
    cudaGetSymbolAddress((void**)&pxl,   g_xl);
    cudaGetSymbolAddress((void**)&pzf,   g_zf);
    cudaGetSymbolAddress((void**)&pgsf,  g_gsf);
    cudaGetSymbolAddress((void**)&pmxf,  g_mxf);
    cudaGetSymbolAddress((void**)&pwch,  g_wch);
    cudaGetSymbolAddress((void**)&pwcl,  g_wcl);

    /* final_state placement (proven in round 3): real-part-only pack  */
    const long base = (long)T_STEPS * OUT_D;                  /* 8388608 */
    const long osz  = (long)out_size;
    float* fs_dst  = pfsd;
    int    fs_mode = 0;
    if (osz == base + CH) {            /* 8389632: real-part-only pack */
        fs_dst  = out + base;
        fs_mode = 1;
    } else if (osz >= base + 2*CH) {
        fs_dst  = out + base;
        fs_mode = 0;
    } else if (2*osz >= base + 2*CH) {
        fs_dst  = out + base;
        fs_mode = 0;
    }

    static int inited = 0;
    if (!inited) {
        cudaFuncSetAttribute(hgemm_dual,        cudaFuncAttributeMaxDynamicSharedMemorySize, DUAL_SMEM);
        cudaFuncSetAttribute(hgemm_small_gated, cudaFuncAttributeMaxDynamicSharedMemorySize, SMALL_SMEM);
        inited = 1;
    }

    /* split + start prep in one launch (trailing block does prep)     */
    split_all<<<SPLIT_BLOCKS + 1, 256>>>(x, gi_w, pre_w, go_w, skip_w, mix_w,
                                         go_b, skip_b, start);

    /* small GEMM + gated + scan-A fused (block j == chunk j)          */
    hgemm_small_gated<<<T_STEPS/64, 256, SMALL_SMEM>>>(pxh, pxl, pwch, pwcl,
                                                       gi_b, pre_b, ffa_a, ffa_b);
    carry_scan<<<128, 256>>>(st_re, st_im, fs_dst, fs_mode);
    expand_kernel<<<NCHUNK, 1024>>>(ffa_a, ffa_b);

    hgemm_dual<<<1536, 256, DUAL_SMEM>>>(pxh, pgsf, pbgs, pgs,
                                         pzf, pmxf, mix_b, pzr);

    ln_kernel<<<T_STEPS, 256>>>(out);
}

// round 14
// speedup vs baseline: 1.1856x; 1.0306x over previous
#include <cuda_runtime.h>
#include <cuda_fp16.h>
#include <stdint.h>

#define T_STEPS 8192
#define INPUT_D 1024
#define TRACE_D 64
#define CTX_D   16
#define OUT_D   1024
#define CH      (TRACE_D*CTX_D)      /* 1024 channels */
#define CHUNK   32
#define NCHUNK  (T_STEPS/CHUNK)      /* 256 */

/* ------------------------------------------------------------------ */
/* scratch (device globals: allocation-free rule)                      */
/* ------------------------------------------------------------------ */
__device__ float  g_gx[T_STEPS*TRACE_D];      /* gated_x                */
__device__ float2 g_Ac[NCHUNK*CH];
__device__ float2 g_Bc[NCHUNK*CH];
__device__ float2 g_carry[NCHUNK*CH];
__device__ float  g_zr [(size_t)T_STEPS*OUT_D];
__device__ float  g_gs [(size_t)T_STEPS*2*OUT_D];   /* go|skip fused, N=2048 */
__device__ unsigned char g_start[T_STEPS];
__device__ float  g_fsdump[2*CH];
__device__ float  g_bgs[2*OUT_D];             /* go_b | skip_b          */

/* fp16 operands for tensor-core GEMMs */
__device__ __half g_xh[(size_t)T_STEPS*INPUT_D];
__device__ __half g_zf[(size_t)T_STEPS*2*CH];
__device__ __half g_gsf[2*OUT_D*INPUT_D];
__device__ __half g_mxf[OUT_D*2*CH];
__device__ __half g_wch[128*INPUT_D];

/* ------------------------------------------------------------------ */
/* PTX helpers                                                         */
/* ------------------------------------------------------------------ */
__device__ __forceinline__ uint32_t smem_u32(const void* p){
    uint32_t a;
    asm("{ .reg .u64 t; cvta.to.shared.u64 t, %1; cvt.u32.u64 %0, t; }"
        : "=r"(a) : "l"(p));
    return a;
}
__device__ __forceinline__ void cpa16(uint32_t s, const void* g){
    asm volatile("cp.async.cg.shared.global [%0], [%1], 16;"
                 :: "r"(s), "l"(g) : "memory");
}
__device__ __forceinline__ void cpa_commit(){
    asm volatile("cp.async.commit_group;" ::: "memory");
}
template<int N>
__device__ __forceinline__ void cpa_wait(){
    asm volatile("cp.async.wait_group %0;" :: "n"(N) : "memory");
}
__device__ __forceinline__ void ldsm4(uint32_t* r, uint32_t a){
    asm volatile("ldmatrix.sync.aligned.m8n8.x4.shared.b16 {%0,%1,%2,%3}, [%4];"
                 : "=r"(r[0]), "=r"(r[1]), "=r"(r[2]), "=r"(r[3]) : "r"(a));
}
__device__ __forceinline__ void mma_f16(float* d, const uint32_t* a, const uint32_t* b){
    asm volatile(
        "mma.sync.aligned.m16n8k16.row.col.f32.f16.f16.f32 "
        "{%0,%1,%2,%3}, {%4,%5,%6,%7}, {%8,%9}, {%0,%1,%2,%3};"
        : "+f"(d[0]), "+f"(d[1]), "+f"(d[2]), "+f"(d[3])
        : "r"(a[0]), "r"(a[1]), "r"(a[2]), "r"(a[3]), "r"(b[0]), "r"(b[1]));
}
__device__ __forceinline__ uint32_t sw128(uint32_t b){
    return b ^ ((b >> 3) & 0x70);
}

#define DUAL_SMEM  (3*32768)                   /* 98304: 2 CTAs/SM      */
#define SMALL_SMEM (3*24576)                   /* 73728                 */

/* ------------------------------------------------------------------ */
/* DUAL big GEMM, fp16 single-pass, fp32 acc (proven config).          */
/* job0 (bid<1024):  g_gs = xh @ gsf^T + bgs   (N=2048, K=1024)        */
/* job1 (bid>=1024): g_zr = zf @ mxf^T + mix_b (N=1024, K=2048)        */
/* ------------------------------------------------------------------ */
__global__ __launch_bounds__(256, 2)
void hgemm_dual(const __half* __restrict__ A0, const __half* __restrict__ W0,
                const float* __restrict__ b0, float* __restrict__ C0,
                const __half* __restrict__ A1, const __half* __restrict__ W1,
                const float* __restrict__ b1, float* __restrict__ C1)
{
    const int TSZ = 16384, STAGE = 32768;
    extern __shared__ char smem[];
    const uint32_t sb = smem_u32(smem);
    const int tid = threadIdx.x;
    const int wid = tid >> 5, l = tid & 31;

    const int bid  = blockIdx.x;
    const bool j1  = (bid >= 1024);
    const int lb   = j1 ? bid - 1024 : bid;
    const int bm   = (lb & 63) * 128;
    const int bn   = (lb >> 6) * 128;
    const int N    = j1 ? OUT_D : 2*OUT_D;
    const int K    = j1 ? 2*CH  : INPUT_D;
    const __half* A = j1 ? A1 : A0;
    const __half* W = j1 ? W1 : W0;
    const float* bias = j1 ? b1 : b0;
    float* C = j1 ? C1 : C0;

    const int wm0 = (wid & 3) * 32, wn0 = (wid >> 2) * 64;

    float acc[2][8][4];
#pragma unroll
    for (int mt = 0; mt < 2; mt++)
#pragma unroll
        for (int nt = 0; nt < 8; nt++)
#pragma unroll
            for (int j = 0; j < 4; j++) acc[mt][nt][j] = 0.f;

    const int nk = K >> 6;

    auto issue = [&](int s, int k0){
        const uint32_t st = sb + s * STAGE;
#pragma unroll
        for (int it = 0; it < 4; it++) {
            int idx = tid + it*256;
            int row = idx >> 3, cv = idx & 7;
            uint32_t sw = sw128((uint32_t)(row*128 + cv*16));
            cpa16(st +       sw, A + (size_t)(bm + row) * K + k0 + cv*8);
            cpa16(st + TSZ + sw, W + (size_t)(bn + row) * K + k0 + cv*8);
        }
        cpa_commit();
    };

    issue(0, 0);
    issue(1, 64);
    for (int kt = 0; kt < nk; kt++) {
        if (kt + 1 < nk) cpa_wait<1>(); else cpa_wait<0>();
        __syncthreads();
        if (kt + 2 < nk) issue((kt+2) % 3, (kt+2) << 6);

        const uint32_t st  = sb + (kt % 3) * STAGE;
        const uint32_t A_s = st, B_s = st + TSZ;

#pragma unroll
        for (int kk = 0; kk < 4; kk++) {
            uint32_t af[2][4];
#pragma unroll
            for (int mt = 0; mt < 2; mt++) {
                int row = wm0 + mt*16 + (l & 15);
                uint32_t sw = sw128((uint32_t)(row*128 + kk*32 + (l >> 4)*16));
                ldsm4(af[mt], A_s + sw);
            }
            uint32_t bf[4][4];
#pragma unroll
            for (int p = 0; p < 4; p++) {
                int row = wn0 + p*16 + ((l >> 4) & 1)*8 + (l & 7);
                uint32_t sw = sw128((uint32_t)(row*128 + kk*32 + ((l >> 3) & 1)*16));
                ldsm4(bf[p], B_s + sw);
            }
#pragma unroll
            for (int mt = 0; mt < 2; mt++)
#pragma unroll
                for (int nt = 0; nt < 8; nt++)
                    mma_f16(acc[mt][nt], af[mt], &bf[nt >> 1][(nt & 1)*2]);
        }
    }

#pragma unroll
    for (int mt = 0; mt < 2; mt++) {
        int row0 = bm + wm0 + mt*16 + (l >> 2);
#pragma unroll
        for (int nt = 0; nt < 8; nt++) {
            int col = bn + wn0 + nt*8 + (l & 3)*2;
            float bb0 = bias[col], bb1 = bias[col+1];
            float* c0 = C + (size_t)row0 * N + col;
            c0[0] = acc[mt][nt][0] + bb0;
            c0[1] = acc[mt][nt][1] + bb1;
            float* c1 = C + (size_t)(row0 + 8) * N + col;
            c1[0] = acc[mt][nt][2] + bb0;
            c1[1] = acc[mt][nt][3] + bb1;
        }
    }
}

/* ------------------------------------------------------------------ */
/* small GEMM (BM=64, N=128, K=1024), fp16 single-pass, FUSED gated    */
/* epilogue AND scan phase-A (block j emits chunks 2j and 2j+1).       */
/* ------------------------------------------------------------------ */
__global__ __launch_bounds__(256, 1)
void hgemm_small_gated(const __half* __restrict__ A, const __half* __restrict__ W,
                       const float* __restrict__ gi_b, const float* __restrict__ pre_b,
                       const float* __restrict__ ffa_a, const float* __restrict__ ffa_b)
{
    const int ASZ = 8192, STAGE = ASZ + 16384, K = INPUT_D;
    extern __shared__ char smem[];
    const uint32_t sb = smem_u32(smem);
    const int tid = threadIdx.x;
    const int wid = tid >> 5, l = tid & 31;
    const int bm = blockIdx.x * 64;
    const int wm0 = (wid & 3) * 16, wn0 = (wid >> 2) * 64;
    const int lr = tid >> 3, lc = tid & 7;

    float acc[8][4];
#pragma unroll
    for (int nt = 0; nt < 8; nt++)
#pragma unroll
        for (int j = 0; j < 4; j++) acc[nt][j] = 0.f;

    const int nk = K >> 6;       /* 16 */

    auto issue = [&](int s, int k0){
        const uint32_t st = sb + s * STAGE;
#pragma unroll
        for (int it = 0; it < 2; it++) {
            int idx = tid + it*256;
            int row = idx >> 3, cv = idx & 7;
            uint32_t sw = sw128((uint32_t)(row*128 + cv*16));
            cpa16(st + sw, A + (size_t)(bm + row) * K + k0 + cv*8);
        }
#pragma unroll
        for (int it = 0; it < 4; it++) {
            int row = lr + it*32, cv = lc;
            uint32_t sw = sw128((uint32_t)(row*128 + cv*16));
            cpa16(st + ASZ + sw, W + (size_t)row * K + k0 + cv*8);
        }
        cpa_commit();
    };

    issue(0, 0);
    issue(1, 64);
    for (int kt = 0; kt < nk; kt++) {
        if (kt + 1 < nk) cpa_wait<1>(); else cpa_wait<0>();
        __syncthreads();
        if (kt + 2 < nk) issue((kt+2) % 3, (kt+2) << 6);

        const uint32_t st  = sb + (kt % 3) * STAGE;
        const uint32_t A_s = st, B_s = st + ASZ;

#pragma unroll
        for (int kk = 0; kk < 4; kk++) {
            uint32_t af[4];
            {
                int row = wm0 + (l & 15);
                uint32_t sw = sw128((uint32_t)(row*128 + kk*32 + (l >> 4)*16));
                ldsm4(af, A_s + sw);
            }
            uint32_t bf[4][4];
#pragma unroll
            for (int p = 0; p < 4; p++) {
                int row = wn0 + p*16 + ((l >> 4) & 1)*8 + (l & 7);
                uint32_t sw = sw128((uint32_t)(row*128 + kk*32 + ((l >> 3) & 1)*16));
                ldsm4(bf[p], B_s + sw);
            }
#pragma unroll
            for (int nt = 0; nt < 8; nt++)
                mma_f16(acc[nt], af, &bf[nt >> 1][(nt & 1)*2]);
        }
    }

    /* ---- fused epilogue 1: stage Y into smem --------------------- */
    __syncthreads();
    float* sY  = (float*)smem;                 /* [64][130]           */
    float* gxs = sY + 64*130;                  /* [64][65] gated_x    */
    unsigned char* ssm = (unsigned char*)(gxs + 64*65);
    const int YS = 130;
    {
        int row0 = wm0 + (l >> 2);
#pragma unroll
        for (int nt = 0; nt < 8; nt++) {
            int col = wn0 + nt*8 + (l & 3)*2;
            sY[row0*YS + col]     = acc[nt][0];
            sY[row0*YS + col + 1] = acc[nt][1];
            sY[(row0+8)*YS + col]     = acc[nt][2];
            sY[(row0+8)*YS + col + 1] = acc[nt][3];
        }
    }
    if (tid < 64) ssm[tid] = g_start[bm + tid];
    __syncthreads();

    /* ---- fused epilogue 2: gated_x -> gmem + smem ---------------- */
    const int m = tid & 63;
    const float gb = gi_b[m], pb = pre_b[m];
#pragma unroll
    for (int i = 0; i < 16; i++) {
        int r = (tid >> 6) + i*4;
        float y1 = sY[r*YS + m]      + gb;
        float y2 = sY[r*YS + 64 + m] + pb;
        float gx = y2 / (1.f + expf(-y1));
        g_gx[(size_t)(bm + r)*TRACE_D + m] = gx;
        gxs[r*65 + m] = gx;
    }
    __syncthreads();

    /* ---- fused epilogue 3: scan phase-A, two 32-step chunks ------ */
    float gr[4], gi_[4];
    int mm[4];
#pragma unroll
    for (int q = 0; q < 4; q++) {
        int ch = tid + q*256;
        mm[q] = ch >> 4;
        int cc = ch & 15;
        float rr = expf(-fabsf(ffa_a[mm[q]]));
        gr[q] = rr * cosf(ffa_b[cc]);
        gi_[q] = rr * sinf(ffa_b[cc]);
    }
#pragma unroll
    for (int seg = 0; seg < 2; seg++) {
        float Ar[4], Ai[4], Br[4], Bi[4];
#pragma unroll
        for (int q = 0; q < 4; q++) { Ar[q] = 1.f; Ai[q] = 0.f; Br[q] = 0.f; Bi[q] = 0.f; }
#pragma unroll 2
        for (int t = seg*32; t < seg*32 + 32; t++) {
            bool st = ssm[t];
#pragma unroll
            for (int q = 0; q < 4; q++) {
                float xv = gxs[t*65 + mm[q]];
                if (st) { Ar[q] = 0.f; Ai[q] = 0.f; Br[q] = xv; Bi[q] = 0.f; }
                else {
                    float nAr = gr[q]*Ar[q] - gi_[q]*Ai[q];
                    float nAi = gr[q]*Ai[q] + gi_[q]*Ar[q];
                    float nBr = gr[q]*Br[q] - gi_[q]*Bi[q] + xv;
                    float nBi = gr[q]*Bi[q] + gi_[q]*Br[q];
                    Ar[q] = nAr; Ai[q] = nAi; Br[q] = nBr; Bi[q] = nBi;
                }
            }
        }
        int chunk = blockIdx.x*2 + seg;
#pragma unroll
        for (int q = 0; q < 4; q++) {
            int ch = tid + q*256;
            g_Ac[chunk*CH + ch] = make_float2(Ar[q], Ai[q]);
            g_Bc[chunk*CH + ch] = make_float2(Br[q], Bi[q]);
        }
    }
}

/* ------------------------------------------------------------------ */
/* merged conversion kernel (+ trailing block does start-flag prep)    */
/* ------------------------------------------------------------------ */
#define XQ  2097152
#define WQ  16384
#define GQ  262144
#define MQ  524288
#define C1q (XQ)
#define C2q (C1q + WQ)
#define C3q (C2q + WQ)
#define C4q (C3q + GQ)
#define C5q (C4q + GQ)
#define C6q (C5q + MQ)
#define CTq (C6q + 512)
#define SPLIT_BLOCKS ((CTq + 255)/256)

__device__ __forceinline__ void cvt_h(const float4* __restrict__ s, long i,
                                      uint2* __restrict__ o)
{
    float4 v = s[i];
    uint2 u;
    u.x = (uint32_t)__half_as_ushort(__float2half(v.x))
        | ((uint32_t)__half_as_ushort(__float2half(v.y)) << 16);
    u.y = (uint32_t)__half_as_ushort(__float2half(v.z))
        | ((uint32_t)__half_as_ushort(__float2half(v.w)) << 16);
    o[i] = u;
}

__global__ void split_all(const float* __restrict__ x,
                          const float* __restrict__ gi_w, const float* __restrict__ pre_w,
                          const float* __restrict__ go_w, const float* __restrict__ skip_w,
                          const float* __restrict__ mix_w,
                          const float* __restrict__ go_b, const float* __restrict__ skip_b,
                          const unsigned char* __restrict__ s8)
{
    /* trailing block: start-flag classify + canonicalize             */
    if (blockIdx.x == SPLIT_BLOCKS) {
        __shared__ int flags[3];
        const int tid = threadIdx.x;
        if (tid < 3) flags[tid] = 0;
        __syncthreads();
        const unsigned int* s32 = (const unsigned int*)s8;
        for (int i = tid; i < 2048; i += 256) {
            unsigned v = s32[i];
            if (v == 0u) continue;
            else if (v == 1u)           atomicOr(&flags[0], 1);
            else if (v == 0x3f800000u)  atomicOr(&flags[1], 1);
            else                        atomicOr(&flags[2], 1);
        }
        __syncthreads();
        const int mode = flags[2] ? 0 : (flags[1] ? 2 : (flags[0] ? 1 : 0));
#pragma unroll
        for (int i = 0; i < 32; i++) {
            int idx = tid + i*256;
            unsigned char v;
            if (mode == 1)      v = (((const int*)  s8)[idx] != 0);
            else if (mode == 2) v = (((const float*)s8)[idx] != 0.f);
            else                v = (s8[idx] != 0);
            g_start[idx] = v;
        }
        return;
    }

    long i = (long)blockIdx.x * blockDim.x + threadIdx.x;
    if (i >= CTq) return;
    if (i < C1q)      cvt_h((const float4*)x,     i,       (uint2*)g_xh);
    else if (i < C2q) cvt_h((const float4*)gi_w,  i - C1q, (uint2*)g_wch);
    else if (i < C3q) cvt_h((const float4*)pre_w, i - C2q, (uint2*)(g_wch + 64*INPUT_D));
    else if (i < C4q) cvt_h((const float4*)go_w,   i - C3q, (uint2*)g_gsf);
    else if (i < C5q) cvt_h((const float4*)skip_w, i - C4q,
                            (uint2*)(g_gsf + (size_t)OUT_D*INPUT_D));
    else if (i < C6q) cvt_h((const float4*)mix_w,  i - C5q, (uint2*)g_mxf);
    else {
        long i2 = i - C6q;
        float4 v = (i2 < 256) ? ((const float4*)go_b)[i2] : ((const float4*)skip_b)[i2 - 256];
        ((float4*)g_bgs)[i2] = v;
    }
}

/* ------------------------------------------------------------------ */
/* Phase B: PARALLEL warp-scan carry. 1 warp per channel; lane owns 8  */
/* chunks (NCHUNK=256). grid=128, block=256.                           */
/* ------------------------------------------------------------------ */
__global__ __launch_bounds__(256)
void carry_scan(const float* __restrict__ st_re, const float* __restrict__ st_im,
                float* __restrict__ out_fs, int fs_mode)
{
    const int tid  = threadIdx.x;
    const int wid  = tid >> 5, lane = tid & 31;
    const int ch   = blockIdx.x * 8 + wid;           /* 0..1023 */
    const unsigned FULL = 0xffffffffu;

    /* load 8 chunk affines, compose serially: f = f7∘...∘f0           */
    float2 a[8], b[8];
#pragma unroll
    for (int u = 0; u < 8; u++) {
        int j = lane*8 + u;
        a[u] = g_Ac[j*CH + ch];
        b[u] = g_Bc[j*CH + ch];
    }
    float Atr = a[0].x, Ati = a[0].y, Btr = b[0].x, Bti = b[0].y;
#pragma unroll
    for (int u = 1; u < 8; u++) {
        float nAr = a[u].x*Atr - a[u].y*Ati;
        float nAi = a[u].x*Ati + a[u].y*Atr;
        float nBr = a[u].x*Btr - a[u].y*Bti + b[u].x;
        float nBi = a[u].x*Bti + a[u].y*Btr + b[u].y;
        Atr = nAr; Ati = nAi; Btr = nBr; Bti = nBi;
    }

    /* Kogge-Stone inclusive scan over lanes: cur = cur ∘ prev         */
#pragma unroll
    for (int off = 1; off < 32; off <<= 1) {
        float pAr = __shfl_up_sync(FULL, Atr, off);
        float pAi = __shfl_up_sync(FULL, Ati, off);
        float pBr = __shfl_up_sync(FULL, Btr, off);
        float pBi = __shfl_up_sync(FULL, Bti, off);
        if (lane >= off) {
            float nAr = Atr*pAr - Ati*pAi;
            float nAi = Atr*pAi + Ati*pAr;
            float nBr = Atr*pBr - Ati*pBi + Btr;
            float nBi = Atr*pBi + Ati*pBr + Bti;
            Atr = nAr; Ati = nAi; Btr = nBr; Bti = nBi;
        }
    }

    /* exclusive = shifted inclusive; identity at lane 0               */
    float eAr = __shfl_up_sync(FULL, Atr, 1);
    float eAi = __shfl_up_sync(FULL, Ati, 1);
    float eBr = __shfl_up_sync(FULL, Btr, 1);
    float eBi = __shfl_up_sync(FULL, Bti, 1);
    if (lane == 0) { eAr = 1.f; eAi = 0.f; eBr = 0.f; eBi = 0.f; }

    /* carry state entering this lane's first chunk                    */
    const float s0r = st_re[ch], s0i = st_im[ch];
    float sr = eAr*s0r - eAi*s0i + eBr;
    float si = eAr*s0i + eAi*s0r + eBi;

    /* replay local chunks: write carry, advance                       */
#pragma unroll
    for (int u = 0; u < 8; u++) {
        int j = lane*8 + u;
        g_carry[j*CH + ch] = make_float2(sr, si);
        float nr = a[u].x*sr - a[u].y*si + b[u].x;
        float ni = a[u].x*si + a[u].y*sr + b[u].y;
        sr = nr; si = ni;
    }

    if (lane == 31) {                    /* final state of channel     */
        if (fs_mode == 1) {
            out_fs[ch] = sr;
        } else {
            out_fs[2*ch]   = sr;
            out_fs[2*ch+1] = si;
        }
    }
}

/* Phase C: replay chunks (CHUNK=32); write z_in fp16 [T, 2048]        */
__global__ __launch_bounds__(1024)
void expand_kernel(const float* __restrict__ ffa_a, const float* __restrict__ ffa_b)
{
    __shared__ float sx[CHUNK*TRACE_D];
    __shared__ unsigned char ss[CHUNK];
    const int chunk = blockIdx.x, tid = threadIdx.x;
    const float* src = g_gx + chunk*CHUNK*TRACE_D;
    for (int i = tid; i < CHUNK*TRACE_D; i += 1024) sx[i] = src[i];
    if (tid < CHUNK) ss[tid] = g_start[chunk*CHUNK + tid];
    __syncthreads();

    const int m = tid >> 4, c = tid & 15;
    const float r  = expf(-fabsf(ffa_a[m]));
    const float gr = r * cosf(ffa_b[c]);
    const float gi = r * sinf(ffa_b[c]);

    float2 s = g_carry[chunk*CH + tid];
    const size_t zo = (size_t)chunk*CHUNK*2*CH + m*32 + c;
#pragma unroll 2
    for (int t = 0; t < CHUNK; t++) {
        float xv = sx[t*TRACE_D + m];
        float nr, ni;
        if (ss[t]) { nr = xv; ni = 0.f; }
        else { nr = gr*s.x - gi*s.y + xv; ni = gr*s.y + gi*s.x; }
        s.x = nr; s.y = ni;
        size_t o = zo + (size_t)t*2048;
        g_zf[o]      = __float2half(nr);
        g_zf[o + 16] = __float2half(ni);
    }
}

/* ------------------------------------------------------------------ */
/* epilogue: zg = z*sig(go); LN(zg) + skip*(1-sig(go)); float4 I/O     */
/* ------------------------------------------------------------------ */
__global__ __launch_bounds__(256)
void ln_kernel(float* __restrict__ out)
{
    const int row = blockIdx.x, tid = threadIdx.x;
    const float4* zp = (const float4*)(g_zr + (size_t)row*OUT_D);
    const float4* gp = (const float4*)(g_gs + (size_t)row*2*OUT_D);
    const float4* sp = (const float4*)(g_gs + (size_t)row*2*OUT_D + OUT_D);

    float4 zv4 = zp[tid], gv4 = gp[tid], sv4 = sp[tid];
    float zg[4], sk[4], s1 = 0.f, s2 = 0.f;
    {
        const float* zv = &zv4.x; const float* gv = &gv4.x; const float* sv = &sv4.x;
#pragma unroll
        for (int i = 0; i < 4; i++) {
            float g  = 1.f / (1.f + expf(-gv[i]));
            float z  = zv[i] * g;
            zg[i] = z; s1 += z; s2 += z*z;
            sk[i] = sv[i] * (1.f - g);
        }
    }
#pragma unroll
    for (int o = 16; o > 0; o >>= 1) {
        s1 += __shfl_xor_sync(0xffffffffu, s1, o);
        s2 += __shfl_xor_sync(0xffffffffu, s2, o);
    }
    __shared__ float sh1[8], sh2[8];
    const int warp = tid >> 5, lane = tid & 31;
    if (lane == 0) { sh1[warp] = s1; sh2[warp] = s2; }
    __syncthreads();
    if (tid == 0) {
        float t1 = 0.f, t2 = 0.f;
        for (int w = 0; w < 8; w++) { t1 += sh1[w]; t2 += sh2[w]; }
        sh1[0] = t1; sh2[0] = t2;
    }
    __syncthreads();
    const float mu   = sh1[0] * (1.f/OUT_D);
    const float var  = sh2[0] * (1.f/OUT_D) - mu*mu;
    const float rstd = rsqrtf(var + 1e-5f);
    float4 o4;
    o4.x = (zg[0] - mu) * rstd + sk[0];
    o4.y = (zg[1] - mu) * rstd + sk[1];
    o4.z = (zg[2] - mu) * rstd + sk[2];
    o4.w = (zg[3] - mu) * rstd + sk[3];
    ((float4*)(out + (size_t)row*OUT_D))[tid] = o4;
}

/* ------------------------------------------------------------------ */
extern "C" void kernel_launch(void* const* d_in, const int* in_sizes, int n_in,
                              void* d_out, int out_size)
{
    (void)in_sizes; (void)n_in;
    const float* x      = (const float*)d_in[0];
    const float* st_re  = (const float*)d_in[1];
    const float* st_im  = (const float*)d_in[2];
    const unsigned char* start = (const unsigned char*)d_in[3];
    const float* pre_w  = (const float*)d_in[5];
    const float* pre_b  = (const float*)d_in[6];
    const float* gi_w   = (const float*)d_in[7];
    const float* gi_b   = (const float*)d_in[8];
    const float* go_w   = (const float*)d_in[9];
    const float* go_b   = (const float*)d_in[10];
    const float* skip_w = (const float*)d_in[11];
    const float* skip_b = (const float*)d_in[12];
    const float* mix_w  = (const float*)d_in[13];
    const float* mix_b  = (const float*)d_in[14];
    const float* ffa_a  = (const float*)d_in[15];
    const float* ffa_b  = (const float*)d_in[16];
    float* out = (float*)d_out;

    float *pzr, *pgs, *pfsd, *pbgs;
    __half *pxh, *pzf, *pgsf, *pmxf, *pwch;
    cudaGetSymbolAddress((void**)&pzr,   g_zr);
    cudaGetSymbolAddress((void**)&pgs,   g_gs);
    cudaGetSymbolAddress((void**)&pfsd,  g_fsdump);
    cudaGetSymbolAddress((void**)&pbgs,  g_bgs);
    cudaGetSymbolAddress((void**)&pxh,   g_xh);
    cudaGetSymbolAddress((void**)&pzf,   g_zf);
    cudaGetSymbolAddress((void**)&pgsf,  g_gsf);
    cudaGetSymbolAddress((void**)&pmxf,  g_mxf);
    cudaGetSymbolAddress((void**)&pwch,  g_wch);

    /* final_state placement (proven in round 3): real-part-only pack  */
    const long base = (long)T_STEPS * OUT_D;                  /* 8388608 */
    const long osz  = (long)out_size;
    float* fs_dst  = pfsd;
    int    fs_mode = 0;
    if (osz == base + CH) {            /* 8389632: real-part-only pack */
        fs_dst  = out + base;
        fs_mode = 1;
    } else if (osz >= base + 2*CH) {
        fs_dst  = out + base;
        fs_mode = 0;
    } else if (2*osz >= base + 2*CH) {
        fs_dst  = out + base;
        fs_mode = 0;
    }

    static int inited = 0;
    if (!inited) {
        cudaFuncSetAttribute(hgemm_dual,        cudaFuncAttributeMaxDynamicSharedMemorySize, DUAL_SMEM);
        cudaFuncSetAttribute(hgemm_small_gated, cudaFuncAttributeMaxDynamicSharedMemorySize, SMALL_SMEM);
        inited = 1;
    }

    /* split + start prep in one launch (trailing block does prep)     */
    split_all<<<SPLIT_BLOCKS + 1, 256>>>(x, gi_w, pre_w, go_w, skip_w, mix_w,
                                         go_b, skip_b, start);

    /* small GEMM + gated + scan-A fused (block j == chunks 2j,2j+1)   */
    hgemm_small_gated<<<T_STEPS/64, 256, SMALL_SMEM>>>(pxh, pwch,
                                                       gi_b, pre_b, ffa_a, ffa_b);
    carry_scan<<<128, 256>>>(st_re, st_im, fs_dst, fs_mode);
    expand_kernel<<<NCHUNK, 1024>>>(ffa_a, ffa_b);

    hgemm_dual<<<1536, 256, DUAL_SMEM>>>(pxh, pgsf, pbgs, pgs,
                                         pzf, pmxf, mix_b, pzr);

    ln_kernel<<<T_STEPS, 256>>>(out);
}

// round 15
// speedup vs baseline: 1.2225x; 1.0312x over previous
#include <cuda_runtime.h>
#include <cuda_fp16.h>
#include <stdint.h>

#define T_STEPS 8192
#define INPUT_D 1024
#define TRACE_D 64
#define CTX_D   16
#define OUT_D   1024
#define CH      (TRACE_D*CTX_D)      /* 1024 channels */
#define CHUNK   32
#define NCHUNK  (T_STEPS/CHUNK)      /* 256 */

/* ------------------------------------------------------------------ */
/* scratch (device globals: allocation-free rule)                      */
/* ------------------------------------------------------------------ */
__device__ float  g_gx[T_STEPS*TRACE_D];      /* gated_x                */
__device__ float2 g_Ac[NCHUNK*CH];
__device__ float2 g_Bc[NCHUNK*CH];
__device__ float2 g_carry[NCHUNK*CH];
__device__ float  g_zr [(size_t)T_STEPS*OUT_D];
__device__ __half g_gs [(size_t)T_STEPS*2*OUT_D];   /* go|skip fp16, N=2048 */
__device__ unsigned char g_start[T_STEPS];
__device__ float  g_fsdump[2*CH];
__device__ float  g_bgs[2*OUT_D];             /* go_b | skip_b          */

/* fp16 operands for tensor-core GEMMs */
__device__ __half g_xh[(size_t)T_STEPS*INPUT_D];
__device__ __half g_zf[(size_t)T_STEPS*2*CH];       /* (re,im) interleaved */
__device__ __half g_gsf[2*OUT_D*INPUT_D];
__device__ __half g_mxf[OUT_D*2*CH];                /* K-permuted to match */
__device__ __half g_wch[128*INPUT_D];

/* ------------------------------------------------------------------ */
/* PTX helpers                                                         */
/* ------------------------------------------------------------------ */
__device__ __forceinline__ uint32_t smem_u32(const void* p){
    uint32_t a;
    asm("{ .reg .u64 t; cvta.to.shared.u64 t, %1; cvt.u32.u64 %0, t; }"
        : "=r"(a) : "l"(p));
    return a;
}
__device__ __forceinline__ void cpa16(uint32_t s, const void* g){
    asm volatile("cp.async.cg.shared.global [%0], [%1], 16;"
                 :: "r"(s), "l"(g) : "memory");
}
__device__ __forceinline__ void cpa_commit(){
    asm volatile("cp.async.commit_group;" ::: "memory");
}
template<int N>
__device__ __forceinline__ void cpa_wait(){
    asm volatile("cp.async.wait_group %0;" :: "n"(N) : "memory");
}
__device__ __forceinline__ void ldsm4(uint32_t* r, uint32_t a){
    asm volatile("ldmatrix.sync.aligned.m8n8.x4.shared.b16 {%0,%1,%2,%3}, [%4];"
                 : "=r"(r[0]), "=r"(r[1]), "=r"(r[2]), "=r"(r[3]) : "r"(a));
}
__device__ __forceinline__ void mma_f16(float* d, const uint32_t* a, const uint32_t* b){
    asm volatile(
        "mma.sync.aligned.m16n8k16.row.col.f32.f16.f16.f32 "
        "{%0,%1,%2,%3}, {%4,%5,%6,%7}, {%8,%9}, {%0,%1,%2,%3};"
        : "+f"(d[0]), "+f"(d[1]), "+f"(d[2]), "+f"(d[3])
        : "r"(a[0]), "r"(a[1]), "r"(a[2]), "r"(a[3]), "r"(b[0]), "r"(b[1]));
}
__device__ __forceinline__ uint32_t sw128(uint32_t b){
    return b ^ ((b >> 3) & 0x70);
}

#define DUAL_SMEM  (3*32768)                   /* 98304: 2 CTAs/SM      */
#define SMALL_SMEM (3*24576)                   /* 73728                 */

/* ------------------------------------------------------------------ */
/* DUAL big GEMM, fp16 single-pass, fp32 acc.                          */
/* job0 (bid<1024):  g_gs(fp16) = xh @ gsf^T + bgs (N=2048, K=1024)    */
/* job1 (bid>=1024): g_zr(fp32) = zf @ mxf^T + mix_b (N=1024, K=2048)  */
/* ------------------------------------------------------------------ */
__global__ __launch_bounds__(256, 2)
void hgemm_dual(const __half* __restrict__ A0, const __half* __restrict__ W0,
                const float* __restrict__ b0, __half* __restrict__ C0,
                const __half* __restrict__ A1, const __half* __restrict__ W1,
                const float* __restrict__ b1, float* __restrict__ C1)
{
    const int TSZ = 16384, STAGE = 32768;
    extern __shared__ char smem[];
    const uint32_t sb = smem_u32(smem);
    const int tid = threadIdx.x;
    const int wid = tid >> 5, l = tid & 31;

    const int bid  = blockIdx.x;
    const bool j1  = (bid >= 1024);
    const int lb   = j1 ? bid - 1024 : bid;
    const int bm   = (lb & 63) * 128;
    const int bn   = (lb >> 6) * 128;
    const int N    = j1 ? OUT_D : 2*OUT_D;
    const int K    = j1 ? 2*CH  : INPUT_D;
    const __half* A = j1 ? A1 : A0;
    const __half* W = j1 ? W1 : W0;
    const float* bias = j1 ? b1 : b0;

    const int wm0 = (wid & 3) * 32, wn0 = (wid >> 2) * 64;

    float acc[2][8][4];
#pragma unroll
    for (int mt = 0; mt < 2; mt++)
#pragma unroll
        for (int nt = 0; nt < 8; nt++)
#pragma unroll
            for (int j = 0; j < 4; j++) acc[mt][nt][j] = 0.f;

    const int nk = K >> 6;

    auto issue = [&](int s, int k0){
        const uint32_t st = sb + s * STAGE;
#pragma unroll
        for (int it = 0; it < 4; it++) {
            int idx = tid + it*256;
            int row = idx >> 3, cv = idx & 7;
            uint32_t sw = sw128((uint32_t)(row*128 + cv*16));
            cpa16(st +       sw, A + (size_t)(bm + row) * K + k0 + cv*8);
            cpa16(st + TSZ + sw, W + (size_t)(bn + row) * K + k0 + cv*8);
        }
        cpa_commit();
    };

    issue(0, 0);
    issue(1, 64);
    for (int kt = 0; kt < nk; kt++) {
        if (kt + 1 < nk) cpa_wait<1>(); else cpa_wait<0>();
        __syncthreads();
        if (kt + 2 < nk) issue((kt+2) % 3, (kt+2) << 6);

        const uint32_t st  = sb + (kt % 3) * STAGE;
        const uint32_t A_s = st, B_s = st + TSZ;

#pragma unroll
        for (int kk = 0; kk < 4; kk++) {
            uint32_t af[2][4];
#pragma unroll
            for (int mt = 0; mt < 2; mt++) {
                int row = wm0 + mt*16 + (l & 15);
                uint32_t sw = sw128((uint32_t)(row*128 + kk*32 + (l >> 4)*16));
                ldsm4(af[mt], A_s + sw);
            }
            uint32_t bf[4][4];
#pragma unroll
            for (int p = 0; p < 4; p++) {
                int row = wn0 + p*16 + ((l >> 4) & 1)*8 + (l & 7);
                uint32_t sw = sw128((uint32_t)(row*128 + kk*32 + ((l >> 3) & 1)*16));
                ldsm4(bf[p], B_s + sw);
            }
#pragma unroll
            for (int mt = 0; mt < 2; mt++)
#pragma unroll
                for (int nt = 0; nt < 8; nt++)
                    mma_f16(acc[mt][nt], af[mt], &bf[nt >> 1][(nt & 1)*2]);
        }
    }

#pragma unroll
    for (int mt = 0; mt < 2; mt++) {
        int row0 = bm + wm0 + mt*16 + (l >> 2);
#pragma unroll
        for (int nt = 0; nt < 8; nt++) {
            int col = bn + wn0 + nt*8 + (l & 3)*2;
            float bb0 = bias[col], bb1 = bias[col+1];
            float v00 = acc[mt][nt][0] + bb0, v01 = acc[mt][nt][1] + bb1;
            float v10 = acc[mt][nt][2] + bb0, v11 = acc[mt][nt][3] + bb1;
            if (j1) {
                float* c0 = C1 + (size_t)row0 * N + col;
                c0[0] = v00; c0[1] = v01;
                float* c1 = C1 + (size_t)(row0 + 8) * N + col;
                c1[0] = v10; c1[1] = v11;
            } else {
                *(__half2*)(C0 + (size_t)row0 * N + col)       = __floats2half2_rn(v00, v01);
                *(__half2*)(C0 + (size_t)(row0 + 8) * N + col) = __floats2half2_rn(v10, v11);
            }
        }
    }
}

/* ------------------------------------------------------------------ */
/* small GEMM (BM=64, N=128, K=1024), fp16 single-pass, FUSED gated    */
/* epilogue AND scan phase-A (block j emits chunks 2j and 2j+1).       */
/* ------------------------------------------------------------------ */
__global__ __launch_bounds__(256, 1)
void hgemm_small_gated(const __half* __restrict__ A, const __half* __restrict__ W,
                       const float* __restrict__ gi_b, const float* __restrict__ pre_b,
                       const float* __restrict__ ffa_a, const float* __restrict__ ffa_b)
{
    const int ASZ = 8192, STAGE = ASZ + 16384, K = INPUT_D;
    extern __shared__ char smem[];
    const uint32_t sb = smem_u32(smem);
    const int tid = threadIdx.x;
    const int wid = tid >> 5, l = tid & 31;
    const int bm = blockIdx.x * 64;
    const int wm0 = (wid & 3) * 16, wn0 = (wid >> 2) * 64;
    const int lr = tid >> 3, lc = tid & 7;

    float acc[8][4];
#pragma unroll
    for (int nt = 0; nt < 8; nt++)
#pragma unroll
        for (int j = 0; j < 4; j++) acc[nt][j] = 0.f;

    const int nk = K >> 6;       /* 16 */

    auto issue = [&](int s, int k0){
        const uint32_t st = sb + s * STAGE;
#pragma unroll
        for (int it = 0; it < 2; it++) {
            int idx = tid + it*256;
            int row = idx >> 3, cv = idx & 7;
            uint32_t sw = sw128((uint32_t)(row*128 + cv*16));
            cpa16(st + sw, A + (size_t)(bm + row) * K + k0 + cv*8);
        }
#pragma unroll
        for (int it = 0; it < 4; it++) {
            int row = lr + it*32, cv = lc;
            uint32_t sw = sw128((uint32_t)(row*128 + cv*16));
            cpa16(st + ASZ + sw, W + (size_t)row * K + k0 + cv*8);
        }
        cpa_commit();
    };

    issue(0, 0);
    issue(1, 64);
    for (int kt = 0; kt < nk; kt++) {
        if (kt + 1 < nk) cpa_wait<1>(); else cpa_wait<0>();
        __syncthreads();
        if (kt + 2 < nk) issue((kt+2) % 3, (kt+2) << 6);

        const uint32_t st  = sb + (kt % 3) * STAGE;
        const uint32_t A_s = st, B_s = st + ASZ;

#pragma unroll
        for (int kk = 0; kk < 4; kk++) {
            uint32_t af[4];
            {
                int row = wm0 + (l & 15);
                uint32_t sw = sw128((uint32_t)(row*128 + kk*32 + (l >> 4)*16));
                ldsm4(af, A_s + sw);
            }
            uint32_t bf[4][4];
#pragma unroll
            for (int p = 0; p < 4; p++) {
                int row = wn0 + p*16 + ((l >> 4) & 1)*8 + (l & 7);
                uint32_t sw = sw128((uint32_t)(row*128 + kk*32 + ((l >> 3) & 1)*16));
                ldsm4(bf[p], B_s + sw);
            }
#pragma unroll
            for (int nt = 0; nt < 8; nt++)
                mma_f16(acc[nt], af, &bf[nt >> 1][(nt & 1)*2]);
        }
    }

    /* ---- fused epilogue 1: stage Y into smem --------------------- */
    __syncthreads();
    float* sY  = (float*)smem;                 /* [64][130]           */
    float* gxs = sY + 64*130;                  /* [64][65] gated_x    */
    unsigned char* ssm = (unsigned char*)(gxs + 64*65);
    const int YS = 130;
    {
        int row0 = wm0 + (l >> 2);
#pragma unroll
        for (int nt = 0; nt < 8; nt++) {
            int col = wn0 + nt*8 + (l & 3)*2;
            sY[row0*YS + col]     = acc[nt][0];
            sY[row0*YS + col + 1] = acc[nt][1];
            sY[(row0+8)*YS + col]     = acc[nt][2];
            sY[(row0+8)*YS + col + 1] = acc[nt][3];
        }
    }
    if (tid < 64) ssm[tid] = g_start[bm + tid];
    __syncthreads();

    /* ---- fused epilogue 2: gated_x -> gmem + smem ---------------- */
    const int m = tid & 63;
    const float gb = gi_b[m], pb = pre_b[m];
#pragma unroll
    for (int i = 0; i < 16; i++) {
        int r = (tid >> 6) + i*4;
        float y1 = sY[r*YS + m]      + gb;
        float y2 = sY[r*YS + 64 + m] + pb;
        float gx = y2 / (1.f + expf(-y1));
        g_gx[(size_t)(bm + r)*TRACE_D + m] = gx;
        gxs[r*65 + m] = gx;
    }
    __syncthreads();

    /* ---- fused epilogue 3: scan phase-A, two 32-step chunks ------ */
    float gr[4], gi_[4];
    int mm[4];
#pragma unroll
    for (int q = 0; q < 4; q++) {
        int ch = tid + q*256;
        mm[q] = ch >> 4;
        int cc = ch & 15;
        float rr = expf(-fabsf(ffa_a[mm[q]]));
        gr[q] = rr * cosf(ffa_b[cc]);
        gi_[q] = rr * sinf(ffa_b[cc]);
    }
#pragma unroll
    for (int seg = 0; seg < 2; seg++) {
        float Ar[4], Ai[4], Br[4], Bi[4];
#pragma unroll
        for (int q = 0; q < 4; q++) { Ar[q] = 1.f; Ai[q] = 0.f; Br[q] = 0.f; Bi[q] = 0.f; }
#pragma unroll 2
        for (int t = seg*32; t < seg*32 + 32; t++) {
            bool st = ssm[t];
#pragma unroll
            for (int q = 0; q < 4; q++) {
                float xv = gxs[t*65 + mm[q]];
                if (st) { Ar[q] = 0.f; Ai[q] = 0.f; Br[q] = xv; Bi[q] = 0.f; }
                else {
                    float nAr = gr[q]*Ar[q] - gi_[q]*Ai[q];
                    float nAi = gr[q]*Ai[q] + gi_[q]*Ar[q];
                    float nBr = gr[q]*Br[q] - gi_[q]*Bi[q] + xv;
                    float nBi = gr[q]*Bi[q] + gi_[q]*Br[q];
                    Ar[q] = nAr; Ai[q] = nAi; Br[q] = nBr; Bi[q] = nBi;
                }
            }
        }
        int chunk = blockIdx.x*2 + seg;
#pragma unroll
        for (int q = 0; q < 4; q++) {
            int ch = tid + q*256;
            g_Ac[chunk*CH + ch] = make_float2(Ar[q], Ai[q]);
            g_Bc[chunk*CH + ch] = make_float2(Br[q], Bi[q]);
        }
    }
}

/* ------------------------------------------------------------------ */
/* merged conversion kernel (+ trailing block does start-flag prep)    */
/* mix_w conversion PERMUTES K columns to the interleaved z layout:    */
/*   new col m*32+2c   <- old col m*32+c      (re)                     */
/*   new col m*32+2c+1 <- old col m*32+16+c   (im)                     */
/* ------------------------------------------------------------------ */
#define XQ  2097152
#define WQ  16384
#define GQ  262144
#define MQ  524288
#define C1q (XQ)
#define C2q (C1q + WQ)
#define C3q (C2q + WQ)
#define C4q (C3q + GQ)
#define C5q (C4q + GQ)
#define C6q (C5q + MQ)
#define CTq (C6q + 512)
#define SPLIT_BLOCKS ((CTq + 255)/256)

__device__ __forceinline__ void cvt_h(const float4* __restrict__ s, long i,
                                      uint2* __restrict__ o)
{
    float4 v = s[i];
    uint2 u;
    u.x = (uint32_t)__half_as_ushort(__float2half(v.x))
        | ((uint32_t)__half_as_ushort(__float2half(v.y)) << 16);
    u.y = (uint32_t)__half_as_ushort(__float2half(v.z))
        | ((uint32_t)__half_as_ushort(__float2half(v.w)) << 16);
    o[i] = u;
}

__global__ void split_all(const float* __restrict__ x,
                          const float* __restrict__ gi_w, const float* __restrict__ pre_w,
                          const float* __restrict__ go_w, const float* __restrict__ skip_w,
                          const float* __restrict__ mix_w,
                          const float* __restrict__ go_b, const float* __restrict__ skip_b,
                          const unsigned char* __restrict__ s8)
{
    /* trailing block: start-flag classify + canonicalize             */
    if (blockIdx.x == SPLIT_BLOCKS) {
        __shared__ int flags[3];
        const int tid = threadIdx.x;
        if (tid < 3) flags[tid] = 0;
        __syncthreads();
        const unsigned int* s32 = (const unsigned int*)s8;
        for (int i = tid; i < 2048; i += 256) {
            unsigned v = s32[i];
            if (v == 0u) continue;
            else if (v == 1u)           atomicOr(&flags[0], 1);
            else if (v == 0x3f800000u)  atomicOr(&flags[1], 1);
            else                        atomicOr(&flags[2], 1);
        }
        __syncthreads();
        const int mode = flags[2] ? 0 : (flags[1] ? 2 : (flags[0] ? 1 : 0));
#pragma unroll
        for (int i = 0; i < 32; i++) {
            int idx = tid + i*256;
            unsigned char v;
            if (mode == 1)      v = (((const int*)  s8)[idx] != 0);
            else if (mode == 2) v = (((const float*)s8)[idx] != 0.f);
            else                v = (s8[idx] != 0);
            g_start[idx] = v;
        }
        return;
    }

    long i = (long)blockIdx.x * blockDim.x + threadIdx.x;
    if (i >= CTq) return;
    if (i < C1q)      cvt_h((const float4*)x,     i,       (uint2*)g_xh);
    else if (i < C2q) cvt_h((const float4*)gi_w,  i - C1q, (uint2*)g_wch);
    else if (i < C3q) cvt_h((const float4*)pre_w, i - C2q, (uint2*)(g_wch + 64*INPUT_D));
    else if (i < C4q) cvt_h((const float4*)go_w,   i - C3q, (uint2*)g_gsf);
    else if (i < C5q) cvt_h((const float4*)skip_w, i - C4q,
                            (uint2*)(g_gsf + (size_t)OUT_D*INPUT_D));
    else if (i < C6q) {
        /* mix weights: gather with K-permutation, 4 new cols / thread */
        long j   = i - C5q;                 /* quad index, 512/row     */
        long row = j >> 9;
        int  n0  = (int)(j & 511) * 4;      /* new col base (mult of 4)*/
        int  mh  = n0 >> 5;                 /* trace block             */
        int  c   = (n0 & 31) >> 1;          /* ctx index (even)        */
        const float* basep = mix_w + row*2048 + mh*32;
        float2 re2 = *(const float2*)(basep + c);
        float2 im2 = *(const float2*)(basep + 16 + c);
        uint2 u;
        u.x = (uint32_t)__half_as_ushort(__float2half(re2.x))
            | ((uint32_t)__half_as_ushort(__float2half(im2.x)) << 16);
        u.y = (uint32_t)__half_as_ushort(__float2half(re2.y))
            | ((uint32_t)__half_as_ushort(__float2half(im2.y)) << 16);
        ((uint2*)g_mxf)[j] = u;
    }
    else {
        long i2 = i - C6q;
        float4 v = (i2 < 256) ? ((const float4*)go_b)[i2] : ((const float4*)skip_b)[i2 - 256];
        ((float4*)g_bgs)[i2] = v;
    }
}

/* ------------------------------------------------------------------ */
/* Phase B: PARALLEL warp-scan carry. 1 warp per channel; lane owns 8  */
/* chunks (NCHUNK=256). grid=128, block=256.                           */
/* ------------------------------------------------------------------ */
__global__ __launch_bounds__(256)
void carry_scan(const float* __restrict__ st_re, const float* __restrict__ st_im,
                float* __restrict__ out_fs, int fs_mode)
{
    const int tid  = threadIdx.x;
    const int wid  = tid >> 5, lane = tid & 31;
    const int ch   = blockIdx.x * 8 + wid;           /* 0..1023 */
    const unsigned FULL = 0xffffffffu;

    float2 a[8], b[8];
#pragma unroll
    for (int u = 0; u < 8; u++) {
        int j = lane*8 + u;
        a[u] = g_Ac[j*CH + ch];
        b[u] = g_Bc[j*CH + ch];
    }
    float Atr = a[0].x, Ati = a[0].y, Btr = b[0].x, Bti = b[0].y;
#pragma unroll
    for (int u = 1; u < 8; u++) {
        float nAr = a[u].x*Atr - a[u].y*Ati;
        float nAi = a[u].x*Ati + a[u].y*Atr;
        float nBr = a[u].x*Btr - a[u].y*Bti + b[u].x;
        float nBi = a[u].x*Bti + a[u].y*Btr + b[u].y;
        Atr = nAr; Ati = nAi; Btr = nBr; Bti = nBi;
    }

#pragma unroll
    for (int off = 1; off < 32; off <<= 1) {
        float pAr = __shfl_up_sync(FULL, Atr, off);
        float pAi = __shfl_up_sync(FULL, Ati, off);
        float pBr = __shfl_up_sync(FULL, Btr, off);
        float pBi = __shfl_up_sync(FULL, Bti, off);
        if (lane >= off) {
            float nAr = Atr*pAr - Ati*pAi;
            float nAi = Atr*pAi + Ati*pAr;
            float nBr = Atr*pBr - Ati*pBi + Btr;
            float nBi = Atr*pBi + Ati*pBr + Bti;
            Atr = nAr; Ati = nAi; Btr = nBr; Bti = nBi;
        }
    }

    float eAr = __shfl_up_sync(FULL, Atr, 1);
    float eAi = __shfl_up_sync(FULL, Ati, 1);
    float eBr = __shfl_up_sync(FULL, Btr, 1);
    float eBi = __shfl_up_sync(FULL, Bti, 1);
    if (lane == 0) { eAr = 1.f; eAi = 0.f; eBr = 0.f; eBi = 0.f; }

    const float s0r = st_re[ch], s0i = st_im[ch];
    float sr = eAr*s0r - eAi*s0i + eBr;
    float si = eAr*s0i + eAi*s0r + eBi;

#pragma unroll
    for (int u = 0; u < 8; u++) {
        int j = lane*8 + u;
        g_carry[j*CH + ch] = make_float2(sr, si);
        float nr = a[u].x*sr - a[u].y*si + b[u].x;
        float ni = a[u].x*si + a[u].y*sr + b[u].y;
        sr = nr; si = ni;
    }

    if (lane == 31) {
        if (fs_mode == 1) {
            out_fs[ch] = sr;
        } else {
            out_fs[2*ch]   = sr;
            out_fs[2*ch+1] = si;
        }
    }
}

/* Phase C: replay chunks (CHUNK=32); write z_in fp16 interleaved      */
/* (re,im) at cols m*32+2c / m*32+2c+1 -> one half2 store per step.    */
__global__ __launch_bounds__(1024)
void expand_kernel(const float* __restrict__ ffa_a, const float* __restrict__ ffa_b)
{
    __shared__ float sx[CHUNK*TRACE_D];
    __shared__ unsigned char ss[CHUNK];
    const int chunk = blockIdx.x, tid = threadIdx.x;
    const float* src = g_gx + chunk*CHUNK*TRACE_D;
    for (int i = tid; i < CHUNK*TRACE_D; i += 1024) sx[i] = src[i];
    if (tid < CHUNK) ss[tid] = g_start[chunk*CHUNK + tid];
    __syncthreads();

    const int m = tid >> 4, c = tid & 15;
    const float r  = expf(-fabsf(ffa_a[m]));
    const float gr = r * cosf(ffa_b[c]);
    const float gi = r * sinf(ffa_b[c]);

    float2 s = g_carry[chunk*CH + tid];
    __half* zb = g_zf + (size_t)chunk*CHUNK*2*CH + m*32 + 2*c;
#pragma unroll 2
    for (int t = 0; t < CHUNK; t++) {
        float xv = sx[t*TRACE_D + m];
        float nr, ni;
        if (ss[t]) { nr = xv; ni = 0.f; }
        else { nr = gr*s.x - gi*s.y + xv; ni = gr*s.y + gi*s.x; }
        s.x = nr; s.y = ni;
        *(__half2*)(zb + (size_t)t*2048) = __floats2half2_rn(nr, ni);
    }
}

/* ------------------------------------------------------------------ */
/* epilogue: zg = z*sig(go); LN(zg) + skip*(1-sig(go))                 */
/* gs is fp16 (uint2 = 4 halves per thread per array)                  */
/* ------------------------------------------------------------------ */
__global__ __launch_bounds__(256)
void ln_kernel(float* __restrict__ out)
{
    const int row = blockIdx.x, tid = threadIdx.x;
    const float4* zp = (const float4*)(g_zr + (size_t)row*OUT_D);
    const uint2*  gp = (const uint2*)(g_gs + (size_t)row*2*OUT_D);

    float4 zv4 = zp[tid];
    uint2 gu = gp[tid];          /* go   cols 4t..4t+3 */
    uint2 su = gp[256 + tid];    /* skip cols 4t..4t+3 */

    float gv[4], sv[4];
    {
        float2 t0 = __half22float2(*(const __half2*)&gu.x);
        float2 t1 = __half22float2(*(const __half2*)&gu.y);
        gv[0] = t0.x; gv[1] = t0.y; gv[2] = t1.x; gv[3] = t1.y;
        float2 t2 = __half22float2(*(const __half2*)&su.x);
        float2 t3 = __half22float2(*(const __half2*)&su.y);
        sv[0] = t2.x; sv[1] = t2.y; sv[2] = t3.x; sv[3] = t3.y;
    }

    float zg[4], sk[4], s1 = 0.f, s2 = 0.f;
    {
        const float* zv = &zv4.x;
#pragma unroll
        for (int i = 0; i < 4; i++) {
            float g  = 1.f / (1.f + expf(-gv[i]));
            float z  = zv[i] * g;
            zg[i] = z; s1 += z; s2 += z*z;
            sk[i] = sv[i] * (1.f - g);
        }
    }
#pragma unroll
    for (int o = 16; o > 0; o >>= 1) {
        s1 += __shfl_xor_sync(0xffffffffu, s1, o);
        s2 += __shfl_xor_sync(0xffffffffu, s2, o);
    }
    __shared__ float sh1[8], sh2[8];
    const int warp = tid >> 5, lane = tid & 31;
    if (lane == 0) { sh1[warp] = s1; sh2[warp] = s2; }
    __syncthreads();
    if (tid == 0) {
        float t1 = 0.f, t2 = 0.f;
        for (int w = 0; w < 8; w++) { t1 += sh1[w]; t2 += sh2[w]; }
        sh1[0] = t1; sh2[0] = t2;
    }
    __syncthreads();
    const float mu   = sh1[0] * (1.f/OUT_D);
    const float var  = sh2[0] * (1.f/OUT_D) - mu*mu;
    const float rstd = rsqrtf(var + 1e-5f);
    float4 o4;
    o4.x = (zg[0] - mu) * rstd + sk[0];
    o4.y = (zg[1] - mu) * rstd + sk[1];
    o4.z = (zg[2] - mu) * rstd + sk[2];
    o4.w = (zg[3] - mu) * rstd + sk[3];
    ((float4*)(out + (size_t)row*OUT_D))[tid] = o4;
}

/* ------------------------------------------------------------------ */
extern "C" void kernel_launch(void* const* d_in, const int* in_sizes, int n_in,
                              void* d_out, int out_size)
{
    (void)in_sizes; (void)n_in;
    const float* x      = (const float*)d_in[0];
    const float* st_re  = (const float*)d_in[1];
    const float* st_im  = (const float*)d_in[2];
    const unsigned char* start = (const unsigned char*)d_in[3];
    const float* pre_w  = (const float*)d_in[5];
    const float* pre_b  = (const float*)d_in[6];
    const float* gi_w   = (const float*)d_in[7];
    const float* gi_b   = (const float*)d_in[8];
    const float* go_w   = (const float*)d_in[9];
    const float* go_b   = (const float*)d_in[10];
    const float* skip_w = (const float*)d_in[11];
    const float* skip_b = (const float*)d_in[12];
    const float* mix_w  = (const float*)d_in[13];
    const float* mix_b  = (const float*)d_in[14];
    const float* ffa_a  = (const float*)d_in[15];
    const float* ffa_b  = (const float*)d_in[16];
    float* out = (float*)d_out;

    float *pzr, *pfsd, *pbgs;
    __half *pgs, *pxh, *pzf, *pgsf, *pmxf, *pwch;
    cudaGetSymbolAddress((void**)&pzr,   g_zr);
    cudaGetSymbolAddress((void**)&pgs,   g_gs);
    cudaGetSymbolAddress((void**)&pfsd,  g_fsdump);
    cudaGetSymbolAddress((void**)&pbgs,  g_bgs);
    cudaGetSymbolAddress((void**)&pxh,   g_xh);
    cudaGetSymbolAddress((void**)&pzf,   g_zf);
    cudaGetSymbolAddress((void**)&pgsf,  g_gsf);
    cudaGetSymbolAddress((void**)&pmxf,  g_mxf);
    cudaGetSymbolAddress((void**)&pwch,  g_wch);

    /* final_state placement (proven in round 3): real-part-only pack  */
    const long base = (long)T_STEPS * OUT_D;                  /* 8388608 */
    const long osz  = (long)out_size;
    float* fs_dst  = pfsd;
    int    fs_mode = 0;
    if (osz == base + CH) {            /* 8389632: real-part-only pack */
        fs_dst  = out + base;
        fs_mode = 1;
    } else if (osz >= base + 2*CH) {
        fs_dst  = out + base;
        fs_mode = 0;
    } else if (2*osz >= base + 2*CH) {
        fs_dst  = out + base;
        fs_mode = 0;
    }

    static int inited = 0;
    if (!inited) {
        cudaFuncSetAttribute(hgemm_dual,        cudaFuncAttributeMaxDynamicSharedMemorySize, DUAL_SMEM);
        cudaFuncSetAttribute(hgemm_small_gated, cudaFuncAttributeMaxDynamicSharedMemorySize, SMALL_SMEM);
        inited = 1;
    }

    /* split + start prep in one launch (trailing block does prep)     */
    split_all<<<SPLIT_BLOCKS + 1, 256>>>(x, gi_w, pre_w, go_w, skip_w, mix_w,
                                         go_b, skip_b, start);

    /* small GEMM + gated + scan-A fused (block j == chunks 2j,2j+1)   */
    hgemm_small_gated<<<T_STEPS/64, 256, SMALL_SMEM>>>(pxh, pwch,
                                                       gi_b, pre_b, ffa_a, ffa_b);
    carry_scan<<<128, 256>>>(st_re, st_im, fs_dst, fs_mode);
    expand_kernel<<<NCHUNK, 1024>>>(ffa_a, ffa_b);

    hgemm_dual<<<1536, 256, DUAL_SMEM>>>(pxh, pgsf, pbgs, pgs,
                                         pzf, pmxf, mix_b, pzr);

    ln_kernel<<<T_STEPS, 256>>>(out);
}